// round 8
// baseline (speedup 1.0000x reference)
#include <cuda_runtime.h>
#include <cuda_bf16.h>
#include <math_constants.h>

// ---------------------------------------------------------------------------
// GroupPooling: per-agent MLP score -> segment softmax over teams ->
// attention-weighted team pooling -> output projection + relu.
// Shapes (fixed dataset): agents=400000, hidden=256, h2=128, teams=100000.
// ---------------------------------------------------------------------------

#define HIDDEN   256
#define H2       128
#define MAX_AGENTS 400000
#define MAX_TEAMS  100000
#define NT 512                 // threads for GEMM kernels (16 warps, 4/SMSP)

// ---- device scratch (static globals; no runtime allocation) ----------------
__device__ float g_scores[MAX_AGENTS];             // scores, then exp values
__device__ int   g_counts[MAX_TEAMS];
__device__ int   g_offs[MAX_TEAMS + 1];
__device__ int   g_bsum[128];                      // block sums for scan
__device__ int   g_order[MAX_AGENTS];
__device__ int   g_idx64;                          // 1 if team_idx is int64
__device__ float g_team_pre[(size_t)MAX_TEAMS * HIDDEN];  // 102.4 MB

// ---- f32x2 packed helpers ---------------------------------------------------
__device__ __forceinline__ unsigned long long pk2(float lo, float hi) {
    unsigned long long r;
    asm("mov.b64 %0, {%1, %2};" : "=l"(r) : "f"(lo), "f"(hi));
    return r;
}
__device__ __forceinline__ float2 upk2(unsigned long long v) {
    float2 r;
    asm("mov.b64 {%0, %1}, %2;" : "=f"(r.x), "=f"(r.y) : "l"(v));
    return r;
}
#define FMA2(acc, a, b) \
    asm("fma.rn.f32x2 %0, %1, %2, %0;" : "+l"(acc) : "l"(a), "l"(b))

// ---------------------------------------------------------------------------
// dtype detection (int64 vs int32 team_idx), deterministic.
// ---------------------------------------------------------------------------
__global__ void k_detect(const void* __restrict__ team_idx, int n_agents,
                         int n_teams) {
    __shared__ int ok_s;
    if (threadIdx.x == 0) ok_s = 1;
    __syncthreads();
    int K = n_agents < 1024 ? n_agents : 1024;
    const long long* p = (const long long*)team_idx;
    for (int i = threadIdx.x; i < K; i += blockDim.x) {
        long long v = p[i];
        if (v < 0 || v >= (long long)n_teams) ok_s = 0;
    }
    __syncthreads();
    if (threadIdx.x == 0) g_idx64 = ok_s;
}

__device__ __forceinline__ int load_team(const void* team_idx, int a,
                                         int n_teams) {
    int t;
    if (g_idx64) t = (int)((const long long*)team_idx)[a];
    else         t = ((const int*)team_idx)[a];
    if (t < 0) t = 0;
    if (t >= n_teams) t = n_teams - 1;
    return t;
}

// ---------------------------------------------------------------------------
// CSR build
// ---------------------------------------------------------------------------
__global__ void k_zero_counts(int n_teams) {
    int i = blockIdx.x * blockDim.x + threadIdx.x;
    if (i < n_teams) g_counts[i] = 0;
}

__global__ void k_count(const void* __restrict__ team_idx, int n_agents,
                        int n_teams) {
    int a = blockIdx.x * blockDim.x + threadIdx.x;
    if (a < n_agents) {
        int t = load_team(team_idx, a, n_teams);
        atomicAdd(&g_counts[t], 1);
    }
}

// parallel scan, 3 kernels: per-block exclusive scan + block sums -> scan of
// block sums (<=128 blocks) -> add offsets.
__global__ void k_scan1(int n_teams) {
    __shared__ int s[1024];
    int tid = threadIdx.x;
    int gid = blockIdx.x * 1024 + tid;
    int v = (gid < n_teams) ? g_counts[gid] : 0;
    s[tid] = v;
    __syncthreads();
    for (int off = 1; off < 1024; off <<= 1) {
        int t2 = (tid >= off) ? s[tid - off] : 0;
        __syncthreads();
        s[tid] += t2;
        __syncthreads();
    }
    if (gid < n_teams) g_offs[gid] = s[tid] - v;   // exclusive within block
    if (tid == 1023) g_bsum[blockIdx.x] = s[1023];
}

__global__ void k_scan2(int nblocks) {
    __shared__ int s[128];
    int tid = threadIdx.x;
    int v = (tid < nblocks) ? g_bsum[tid] : 0;
    s[tid] = v;
    __syncthreads();
    for (int off = 1; off < 128; off <<= 1) {
        int t2 = (tid >= off) ? s[tid - off] : 0;
        __syncthreads();
        s[tid] += t2;
        __syncthreads();
    }
    g_bsum[tid] = s[tid] - v;                      // exclusive
}

__global__ void k_scan3(int n_teams) {
    int gid = blockIdx.x * 1024 + threadIdx.x;
    if (gid < n_teams) g_offs[gid] += g_bsum[blockIdx.x];
}

__global__ void k_fill(const void* __restrict__ team_idx, int n_agents,
                       int n_teams) {
    int a = blockIdx.x * blockDim.x + threadIdx.x;
    if (a < n_agents) {
        int t = load_team(team_idx, a, n_teams);
        int pos = atomicAdd(&g_offs[t], 1);   // g_offs[t] becomes END of team t
        g_order[pos] = a;
    }
}

// ---------------------------------------------------------------------------
// k_scores: scores[a] = W2 . tanh(W1^T x_a + b1) + b2
// 512 threads = 16 warps (4/SMSP). Each warp: 4 agents x 128 cols.
// Each lane: 4 cols x 4 agents. W1 resident in smem (128 KB).
// x staged per-group-transposed: xs[group(16)][k(256)][4 agents] (64 KB).
// Inner loop per k: 2x LDS.128 + 4 mov + 8 FMA2 -> FMA-pipe saturated.
// ---------------------------------------------------------------------------
__global__ __launch_bounds__(NT, 1)
void k_scores(const float* __restrict__ agent_h,
              const float* __restrict__ W1,
              const float* __restrict__ b1,
              const float* __restrict__ W2,
              const float* __restrict__ b2,
              int n_agents) {
    extern __shared__ float smem[];
    float* W1s = smem;                 // 256*128 floats
    float* xs  = smem + HIDDEN * H2;   // 16*256*4 floats

    const int tid    = threadIdx.x;
    const int warpId = tid >> 5;
    const int lane   = tid & 31;
    const int colBase = 4 * lane;

    // stage W1 into smem
    {
        const float4* src = (const float4*)W1;
        float4* dst = (float4*)W1s;
        for (int k = tid; k < (HIDDEN * H2) / 4; k += NT) dst[k] = src[k];
    }

    const float4 b1v = ((const float4*)b1)[lane];
    const float4 w2v = ((const float4*)W2)[lane];
    const float  b2s = __ldg(b2);

    for (int base = blockIdx.x * 64; base < n_agents; base += gridDim.x * 64) {
        __syncthreads();   // covers W1 staging (iter 0) and xs reuse (iter >0)
        // stage 64 agent rows, transposed per 4-agent group
        for (int v = tid; v < 4096; v += NT) {
            int agent = v >> 6;                // 0..63
            int k4    = v & 63;
            int r     = base + agent;
            float4 x4 = (r < n_agents) ? ((const float4*)agent_h)[(size_t)r * 64 + k4]
                                       : make_float4(0.f, 0.f, 0.f, 0.f);
            float* dp = xs + (agent >> 2) * 1024 + (agent & 3);
            int kk = 4 * k4;
            dp[(kk + 0) * 4] = x4.x;
            dp[(kk + 1) * 4] = x4.y;
            dp[(kk + 2) * 4] = x4.z;
            dp[(kk + 3) * 4] = x4.w;
        }
        __syncthreads();

        unsigned long long accA[4], accB[4];
#pragma unroll
        for (int a = 0; a < 4; a++) { accA[a] = 0ull; accB[a] = 0ull; }

        const float* xg = xs + warpId * 1024;

#pragma unroll 8
        for (int k = 0; k < HIDDEN; k++) {
            float4 w4 = *(const float4*)&W1s[k * H2 + colBase];
            float4 xp = *(const float4*)&xg[k * 4];      // broadcast: 4 agents
            unsigned long long wA = pk2(w4.x, w4.y);
            unsigned long long wB = pk2(w4.z, w4.w);
            unsigned long long xd;
            xd = pk2(xp.x, xp.x); FMA2(accA[0], xd, wA); FMA2(accB[0], xd, wB);
            xd = pk2(xp.y, xp.y); FMA2(accA[1], xd, wA); FMA2(accB[1], xd, wB);
            xd = pk2(xp.z, xp.z); FMA2(accA[2], xd, wA); FMA2(accB[2], xd, wB);
            xd = pk2(xp.w, xp.w); FMA2(accA[3], xd, wA); FMA2(accB[3], xd, wB);
        }

#pragma unroll
        for (int a = 0; a < 4; a++) {
            float2 hA = upk2(accA[a]);
            float2 hB = upk2(accB[a]);
            float h0 = tanhf(hA.x + b1v.x);
            float h1 = tanhf(hA.y + b1v.y);
            float h2 = tanhf(hB.x + b1v.z);
            float h3 = tanhf(hB.y + b1v.w);
            float sp = h0 * w2v.x + h1 * w2v.y + h2 * w2v.z + h3 * w2v.w;
#pragma unroll
            for (int o = 16; o > 0; o >>= 1)
                sp += __shfl_xor_sync(0xFFFFFFFFu, sp, o);
            int row = base + warpId * 4 + a;
            if (lane == 0 && row < n_agents) g_scores[row] = sp + b2s;
        }
    }
}

// ---------------------------------------------------------------------------
// k_team: one warp per team. Segment softmax over its agents + weighted pool.
// ---------------------------------------------------------------------------
__global__ void k_team(const float* __restrict__ agent_h,
                       float* __restrict__ out_attn,
                       int n_teams) {
    int t = blockIdx.x * 8 + (threadIdx.x >> 5);
    int lane = threadIdx.x & 31;
    if (t >= n_teams) return;

    int end   = g_offs[t];
    int cnt   = g_counts[t];
    int start = end - cnt;

    // per-team max
    float m = -CUDART_INF_F;
    for (int b = 0; b < cnt; b += 32) {
        int i = b + lane;
        float s = (i < cnt) ? g_scores[g_order[start + i]] : -CUDART_INF_F;
        m = fmaxf(m, s);
    }
#pragma unroll
    for (int o = 16; o > 0; o >>= 1)
        m = fmaxf(m, __shfl_xor_sync(0xFFFFFFFFu, m, o));

    // exp + sum (store e back into g_scores)
    float esum = 0.f;
    for (int b = 0; b < cnt; b += 32) {
        int i = b + lane;
        if (i < cnt) {
            int a = g_order[start + i];
            float e = expf(g_scores[a] - m);
            g_scores[a] = e;
            esum += e;
        }
    }
#pragma unroll
    for (int o = 16; o > 0; o >>= 1)
        esum += __shfl_xor_sync(0xFFFFFFFFu, esum, o);
    __syncwarp();

    float inv = (cnt > 0) ? (1.f / esum) : 0.f;

    float4 acc0 = make_float4(0.f, 0.f, 0.f, 0.f);
    float4 acc1 = make_float4(0.f, 0.f, 0.f, 0.f);
    for (int mI = 0; mI < cnt; mI++) {
        int a = g_order[start + mI];
        float wgt = g_scores[a] * inv;
        if (lane == 0) out_attn[a] = wgt;
        const float4* row = (const float4*)(agent_h + (size_t)a * HIDDEN);
        float4 x0 = row[lane];
        float4 x1 = row[32 + lane];
        acc0.x += wgt * x0.x; acc0.y += wgt * x0.y;
        acc0.z += wgt * x0.z; acc0.w += wgt * x0.w;
        acc1.x += wgt * x1.x; acc1.y += wgt * x1.y;
        acc1.z += wgt * x1.z; acc1.w += wgt * x1.w;
    }
    float4* dst = (float4*)(g_team_pre + (size_t)t * HIDDEN);
    dst[lane]      = acc0;
    dst[32 + lane] = acc1;
}

// ---------------------------------------------------------------------------
// k_out: out = relu(team_pre @ Wo + bo). gridDim.y selects the column half
// (128 cols => 128 KB of Wo in smem). Same structure as k_scores.
// ---------------------------------------------------------------------------
__global__ __launch_bounds__(NT, 1)
void k_out(const float* __restrict__ Wo,
           const float* __restrict__ bo,
           float* __restrict__ out_team,
           int n_teams) {
    extern __shared__ float smem[];
    float* Wos = smem;                 // 256*128 floats (half of Wo cols)
    float* xs  = smem + HIDDEN * H2;   // 16*256*4 floats

    const int tid    = threadIdx.x;
    const int warpId = tid >> 5;
    const int lane   = tid & 31;
    const int colBase = 4 * lane;
    const int H = blockIdx.y;          // 0 or 1

    // stage Wo[:, H*128 .. H*128+127] into smem
    {
        const float4* src = (const float4*)Wo;
        float4* dst = (float4*)Wos;
        for (int v = tid; v < 8192; v += NT) {
            int row = v >> 5;          // 32 float4 per smem row
            int c   = v & 31;
            dst[v] = src[row * 64 + H * 32 + c];
        }
    }

    const float4 bov = ((const float4*)bo)[H * 32 + lane];

    for (int base = blockIdx.x * 64; base < n_teams; base += gridDim.x * 64) {
        __syncthreads();
        for (int v = tid; v < 4096; v += NT) {
            int agent = v >> 6;
            int k4    = v & 63;
            int r     = base + agent;
            float4 x4 = (r < n_teams) ? ((const float4*)g_team_pre)[(size_t)r * 64 + k4]
                                      : make_float4(0.f, 0.f, 0.f, 0.f);
            float* dp = xs + (agent >> 2) * 1024 + (agent & 3);
            int kk = 4 * k4;
            dp[(kk + 0) * 4] = x4.x;
            dp[(kk + 1) * 4] = x4.y;
            dp[(kk + 2) * 4] = x4.z;
            dp[(kk + 3) * 4] = x4.w;
        }
        __syncthreads();

        unsigned long long accA[4], accB[4];
#pragma unroll
        for (int a = 0; a < 4; a++) { accA[a] = 0ull; accB[a] = 0ull; }

        const float* xg = xs + warpId * 1024;

#pragma unroll 8
        for (int k = 0; k < HIDDEN; k++) {
            float4 w4 = *(const float4*)&Wos[k * H2 + colBase];
            float4 xp = *(const float4*)&xg[k * 4];
            unsigned long long wA = pk2(w4.x, w4.y);
            unsigned long long wB = pk2(w4.z, w4.w);
            unsigned long long xd;
            xd = pk2(xp.x, xp.x); FMA2(accA[0], xd, wA); FMA2(accB[0], xd, wB);
            xd = pk2(xp.y, xp.y); FMA2(accA[1], xd, wA); FMA2(accB[1], xd, wB);
            xd = pk2(xp.z, xp.z); FMA2(accA[2], xd, wA); FMA2(accB[2], xd, wB);
            xd = pk2(xp.w, xp.w); FMA2(accA[3], xd, wA); FMA2(accB[3], xd, wB);
        }

#pragma unroll
        for (int a = 0; a < 4; a++) {
            int row = base + warpId * 4 + a;
            if (row < n_teams) {
                float2 oA = upk2(accA[a]);
                float2 oB = upk2(accB[a]);
                float4 o;
                o.x = fmaxf(oA.x + bov.x, 0.f);
                o.y = fmaxf(oA.y + bov.y, 0.f);
                o.z = fmaxf(oB.x + bov.z, 0.f);
                o.w = fmaxf(oB.y + bov.w, 0.f);
                *(float4*)(out_team + (size_t)row * HIDDEN + H * H2 + colBase) = o;
            }
        }
    }
}

// ---------------------------------------------------------------------------
extern "C" void kernel_launch(void* const* d_in, const int* in_sizes, int n_in,
                              void* d_out, int out_size) {
    const float* agent_h  = (const float*)d_in[0];
    const void*  team_idx = d_in[1];   // int32 or int64 -> detected on device
    const float* W1 = (const float*)d_in[3];
    const float* b1 = (const float*)d_in[4];
    const float* W2 = (const float*)d_in[5];
    const float* b2 = (const float*)d_in[6];
    const float* Wo = (const float*)d_in[7];
    const float* bo = (const float*)d_in[8];

    const int n_agents = in_sizes[0] / HIDDEN;
    const int n_teams  = (out_size - n_agents) / HIDDEN;

    float* out_team = (float*)d_out;
    float* out_attn = out_team + (size_t)n_teams * HIDDEN;

    const int SMEM_BYTES = (HIDDEN * H2 + 16 * HIDDEN * 4) * sizeof(float); // 196608
    cudaFuncSetAttribute(k_scores, cudaFuncAttributeMaxDynamicSharedMemorySize,
                         SMEM_BYTES);
    cudaFuncSetAttribute(k_out, cudaFuncAttributeMaxDynamicSharedMemorySize,
                         SMEM_BYTES);

    // dtype detect + CSR build
    const int nscan = (n_teams + 1023) / 1024;
    k_detect<<<1, 256>>>(team_idx, n_agents, n_teams);
    k_zero_counts<<<(n_teams + 255) / 256, 256>>>(n_teams);
    k_count<<<(n_agents + 255) / 256, 256>>>(team_idx, n_agents, n_teams);
    k_scan1<<<nscan, 1024>>>(n_teams);
    k_scan2<<<1, 128>>>(nscan);
    k_scan3<<<nscan, 1024>>>(n_teams);
    k_fill<<<(n_agents + 255) / 256, 256>>>(team_idx, n_agents, n_teams);

    // per-agent scores
    k_scores<<<148, NT, SMEM_BYTES>>>(agent_h, W1, b1, W2, b2, n_agents);

    // segment softmax + weighted pooling (also writes attn output)
    k_team<<<(n_teams + 7) / 8, 256>>>(agent_h, out_attn, n_teams);

    // output projection + relu
    dim3 og(74, 2, 1);
    k_out<<<og, NT, SMEM_BYTES>>>(Wo, bo, out_team, n_teams);
}

// round 10
// speedup vs baseline: 1.1448x; 1.1448x over previous
#include <cuda_runtime.h>
#include <cuda_bf16.h>
#include <math_constants.h>

// ---------------------------------------------------------------------------
// GroupPooling: per-agent MLP score -> segment softmax over teams ->
// attention-weighted team pooling -> output projection + relu.
// Shapes (fixed dataset): agents=400000, hidden=256, h2=128, teams=100000.
// ---------------------------------------------------------------------------

#define HIDDEN   256
#define H2       128
#define MAX_AGENTS 400000
#define MAX_TEAMS  100000
#define NT 512                 // 16 warps, 4/SMSP

typedef unsigned long long ull;

// ---- device scratch (static globals; no runtime allocation) ----------------
__device__ float g_scores[MAX_AGENTS];             // scores, then exp values
__device__ int   g_counts[MAX_TEAMS];
__device__ int   g_offs[MAX_TEAMS + 1];
__device__ int   g_bsum[128];                      // block sums for scan
__device__ int   g_order[MAX_AGENTS];
__device__ int   g_idx64;                          // 1 if team_idx is int64
__device__ float g_team_pre[(size_t)MAX_TEAMS * HIDDEN];  // 102.4 MB

// ---- f32x2 packed helpers ---------------------------------------------------
__device__ __forceinline__ float2 upk2(ull v) {
    float2 r;
    asm("mov.b64 {%0, %1}, %2;" : "=f"(r.x), "=f"(r.y) : "l"(v));
    return r;
}
__device__ __forceinline__ ull swap64(ull v) {
    ull r;
    asm("{ .reg .b32 lo, hi;\n\t"
        "  mov.b64 {lo, hi}, %1;\n\t"
        "  mov.b64 %0, {hi, lo}; }" : "=l"(r) : "l"(v));
    return r;
}
#define FMA2(acc, a, b) \
    asm("fma.rn.f32x2 %0, %1, %2, %0;" : "+l"(acc) : "l"(a), "l"(b))

// ---------------------------------------------------------------------------
// dtype detection (int64 vs int32 team_idx), deterministic.
// ---------------------------------------------------------------------------
__global__ void k_detect(const void* __restrict__ team_idx, int n_agents,
                         int n_teams) {
    __shared__ int ok_s;
    if (threadIdx.x == 0) ok_s = 1;
    __syncthreads();
    int K = n_agents < 1024 ? n_agents : 1024;
    const long long* p = (const long long*)team_idx;
    for (int i = threadIdx.x; i < K; i += blockDim.x) {
        long long v = p[i];
        if (v < 0 || v >= (long long)n_teams) ok_s = 0;
    }
    __syncthreads();
    if (threadIdx.x == 0) g_idx64 = ok_s;
}

__device__ __forceinline__ int load_team(const void* team_idx, int a,
                                         int n_teams) {
    int t;
    if (g_idx64) t = (int)((const long long*)team_idx)[a];
    else         t = ((const int*)team_idx)[a];
    if (t < 0) t = 0;
    if (t >= n_teams) t = n_teams - 1;
    return t;
}

// ---------------------------------------------------------------------------
// CSR build
// ---------------------------------------------------------------------------
__global__ void k_zero_counts(int n_teams) {
    int i = blockIdx.x * blockDim.x + threadIdx.x;
    if (i < n_teams) g_counts[i] = 0;
}

__global__ void k_count(const void* __restrict__ team_idx, int n_agents,
                        int n_teams) {
    int a = blockIdx.x * blockDim.x + threadIdx.x;
    if (a < n_agents) {
        int t = load_team(team_idx, a, n_teams);
        atomicAdd(&g_counts[t], 1);
    }
}

__global__ void k_scan1(int n_teams) {
    __shared__ int s[1024];
    int tid = threadIdx.x;
    int gid = blockIdx.x * 1024 + tid;
    int v = (gid < n_teams) ? g_counts[gid] : 0;
    s[tid] = v;
    __syncthreads();
    for (int off = 1; off < 1024; off <<= 1) {
        int t2 = (tid >= off) ? s[tid - off] : 0;
        __syncthreads();
        s[tid] += t2;
        __syncthreads();
    }
    if (gid < n_teams) g_offs[gid] = s[tid] - v;
    if (tid == 1023) g_bsum[blockIdx.x] = s[1023];
}

__global__ void k_scan2(int nblocks) {
    __shared__ int s[128];
    int tid = threadIdx.x;
    int v = (tid < nblocks) ? g_bsum[tid] : 0;
    s[tid] = v;
    __syncthreads();
    for (int off = 1; off < 128; off <<= 1) {
        int t2 = (tid >= off) ? s[tid - off] : 0;
        __syncthreads();
        s[tid] += t2;
        __syncthreads();
    }
    g_bsum[tid] = s[tid] - v;
}

__global__ void k_scan3(int n_teams) {
    int gid = blockIdx.x * 1024 + threadIdx.x;
    if (gid < n_teams) g_offs[gid] += g_bsum[blockIdx.x];
}

__global__ void k_fill(const void* __restrict__ team_idx, int n_agents,
                       int n_teams) {
    int a = blockIdx.x * blockDim.x + threadIdx.x;
    if (a < n_agents) {
        int t = load_team(team_idx, a, n_teams);
        int pos = atomicAdd(&g_offs[t], 1);
        g_order[pos] = a;
    }
}

// ---------------------------------------------------------------------------
// Shared staging: 64 rows of src into xs with agent-pair XOR swizzle.
// xs layout: xs[k*64 + col'] where col' = ((p ^ (k4&15))<<1)|a0,
// p = agent>>1, a0 = agent&1, k4 = k>>2. Read side (GEMM): lane l at row k
// loads LDS.64 at xs[k*64 + ((l ^ ((k>>2)&15))<<1)] -> packed (x_{2l}, x_{2l+1}).
// ---------------------------------------------------------------------------
__device__ __forceinline__ void stage_tile(float* xs, const float4* g4,
                                           int base, int n_rows, int tid) {
    for (int v = tid; v < 4096; v += NT) {
        int agent = v >> 6;                // 0..63
        int k4    = v & 63;
        int r     = base + agent;
        float4 x4 = (r < n_rows) ? g4[(size_t)r * 64 + k4]
                                 : make_float4(0.f, 0.f, 0.f, 0.f);
        int p  = agent >> 1;
        int a0 = agent & 1;
        int colp = (((p ^ (k4 & 15)) << 1) | a0);
        float* dp = xs + colp;
        int kk = 4 * k4;
        dp[(kk + 0) * 64] = x4.x;
        dp[(kk + 1) * 64] = x4.y;
        dp[(kk + 2) * 64] = x4.z;
        dp[(kk + 3) * 64] = x4.w;
    }
}

// Mixed-accumulator inner product over k=0..255.
// accF[j] = (a*w_{2j}   , b*w_{2j+1});  accS[j] = (b*w_{2j}, a*w_{2j+1})
__device__ __forceinline__ void gemm_core(const float* __restrict__ Ws,
                                          const float* __restrict__ xs,
                                          int c, int lane,
                                          ull accF[4], ull accS[4]) {
#pragma unroll
    for (int j = 0; j < 4; j++) { accF[j] = 0ull; accS[j] = 0ull; }
    const float* wbase = Ws + 8 * c;
#pragma unroll 8
    for (int k = 0; k < HIDDEN; k++) {
        ulonglong2 wv  = *(const ulonglong2*)(wbase + k * H2);      // (w0,w1),(w2,w3)
        ulonglong2 wv2 = *(const ulonglong2*)(wbase + k * H2 + 4);  // (w4,w5),(w6,w7)
        int F = (k >> 2) & 15;
        ull x  = *(const ull*)&xs[k * 64 + ((lane ^ F) << 1)];      // (xa,xb)
        ull xr = swap64(x);                                         // (xb,xa)
        FMA2(accF[0], x,  wv.x);  FMA2(accS[0], xr, wv.x);
        FMA2(accF[1], x,  wv.y);  FMA2(accS[1], xr, wv.y);
        FMA2(accF[2], x,  wv2.x); FMA2(accS[2], xr, wv2.x);
        FMA2(accF[3], x,  wv2.y); FMA2(accS[3], xr, wv2.y);
    }
}

// ---------------------------------------------------------------------------
// k_scores: scores[a] = W2 . tanh(W1^T x_a + b1) + b2
// 16 warps = 16 col-groups of 8 cols; lane owns agents (2l, 2l+1).
// Cross-warp score reduction via smem partials.
// ---------------------------------------------------------------------------
__global__ __launch_bounds__(NT, 1)
void k_scores(const float* __restrict__ agent_h,
              const float* __restrict__ W1,
              const float* __restrict__ b1,
              const float* __restrict__ W2,
              const float* __restrict__ b2,
              int n_agents) {
    extern __shared__ float smem[];
    float* W1s = smem;                      // 256*128 = 128 KB
    float* xs  = smem + HIDDEN * H2;        // 256*64  = 64 KB
    float* ps  = xs + HIDDEN * 64;          // 16*64   = 4 KB

    const int tid  = threadIdx.x;
    const int c    = tid >> 5;              // col group 0..15
    const int lane = tid & 31;

    {   // stage W1
        const float4* src = (const float4*)W1;
        float4* dst = (float4*)W1s;
        for (int k = tid; k < (HIDDEN * H2) / 4; k += NT) dst[k] = src[k];
    }

    const float4 b1a = *(const float4*)&b1[8 * c];
    const float4 b1b = *(const float4*)&b1[8 * c + 4];
    const float4 w2a = *(const float4*)&W2[8 * c];
    const float4 w2b = *(const float4*)&W2[8 * c + 4];
    const float  b2s = __ldg(b2);

    for (int base = blockIdx.x * 64; base < n_agents; base += gridDim.x * 64) {
        __syncthreads();   // protects xs/ps reuse + W1 staging on iter 0
        stage_tile(xs, (const float4*)agent_h, base, n_agents, tid);
        __syncthreads();

        ull accF[4], accS[4];
        gemm_core(W1s, xs, c, lane, accF, accS);

        float2 f0 = upk2(accF[0]), s0 = upk2(accS[0]);
        float2 f1 = upk2(accF[1]), s1 = upk2(accS[1]);
        float2 f2 = upk2(accF[2]), s2 = upk2(accS[2]);
        float2 f3 = upk2(accF[3]), s3 = upk2(accS[3]);

        // agent a = base+2*lane: cols 2j -> accF[j].lo, 2j+1 -> accS[j].hi
        float pa = tanhf(f0.x + b1a.x) * w2a.x + tanhf(s0.y + b1a.y) * w2a.y
                 + tanhf(f1.x + b1a.z) * w2a.z + tanhf(s1.y + b1a.w) * w2a.w
                 + tanhf(f2.x + b1b.x) * w2b.x + tanhf(s2.y + b1b.y) * w2b.y
                 + tanhf(f3.x + b1b.z) * w2b.z + tanhf(s3.y + b1b.w) * w2b.w;
        // agent b = base+2*lane+1: cols 2j -> accS[j].lo, 2j+1 -> accF[j].hi
        float pb = tanhf(s0.x + b1a.x) * w2a.x + tanhf(f0.y + b1a.y) * w2a.y
                 + tanhf(s1.x + b1a.z) * w2a.z + tanhf(f1.y + b1a.w) * w2a.w
                 + tanhf(s2.x + b1b.x) * w2b.x + tanhf(f2.y + b1b.y) * w2b.y
                 + tanhf(s3.x + b1b.z) * w2b.z + tanhf(f3.y + b1b.w) * w2b.w;

        ps[c * 64 + 2 * lane]     = pa;
        ps[c * 64 + 2 * lane + 1] = pb;
        __syncthreads();

        if (tid < 64) {
            float s = b2s;
#pragma unroll
            for (int cc = 0; cc < 16; cc++) s += ps[cc * 64 + tid];
            int row = base + tid;
            if (row < n_agents) g_scores[row] = s;
        }
    }
}

// ---------------------------------------------------------------------------
// k_team: one warp per team. Segment softmax over its agents + weighted pool.
// ---------------------------------------------------------------------------
__global__ void k_team(const float* __restrict__ agent_h,
                       float* __restrict__ out_attn,
                       int n_teams) {
    int t = blockIdx.x * 8 + (threadIdx.x >> 5);
    int lane = threadIdx.x & 31;
    if (t >= n_teams) return;

    int end   = g_offs[t];
    int cnt   = g_counts[t];
    int start = end - cnt;

    float m = -CUDART_INF_F;
    for (int b = 0; b < cnt; b += 32) {
        int i = b + lane;
        float s = (i < cnt) ? g_scores[g_order[start + i]] : -CUDART_INF_F;
        m = fmaxf(m, s);
    }
#pragma unroll
    for (int o = 16; o > 0; o >>= 1)
        m = fmaxf(m, __shfl_xor_sync(0xFFFFFFFFu, m, o));

    float esum = 0.f;
    for (int b = 0; b < cnt; b += 32) {
        int i = b + lane;
        if (i < cnt) {
            int a = g_order[start + i];
            float e = expf(g_scores[a] - m);
            g_scores[a] = e;
            esum += e;
        }
    }
#pragma unroll
    for (int o = 16; o > 0; o >>= 1)
        esum += __shfl_xor_sync(0xFFFFFFFFu, esum, o);
    __syncwarp();

    float inv = (cnt > 0) ? (1.f / esum) : 0.f;

    float4 acc0 = make_float4(0.f, 0.f, 0.f, 0.f);
    float4 acc1 = make_float4(0.f, 0.f, 0.f, 0.f);
    for (int mI = 0; mI < cnt; mI++) {
        int a = g_order[start + mI];
        float wgt = g_scores[a] * inv;
        if (lane == 0) out_attn[a] = wgt;
        const float4* row = (const float4*)(agent_h + (size_t)a * HIDDEN);
        float4 x0 = row[lane];
        float4 x1 = row[32 + lane];
        acc0.x += wgt * x0.x; acc0.y += wgt * x0.y;
        acc0.z += wgt * x0.z; acc0.w += wgt * x0.w;
        acc1.x += wgt * x1.x; acc1.y += wgt * x1.y;
        acc1.z += wgt * x1.z; acc1.w += wgt * x1.w;
    }
    float4* dst = (float4*)(g_team_pre + (size_t)t * HIDDEN);
    dst[lane]      = acc0;
    dst[32 + lane] = acc1;
}

// ---------------------------------------------------------------------------
// k_out: out = relu(team_pre @ Wo + bo). gridDim.y = column half.
// Same mixed-accumulator core; epilogue writes 2 rows x 8 cols per lane.
// ---------------------------------------------------------------------------
__global__ __launch_bounds__(NT, 1)
void k_out(const float* __restrict__ Wo,
           const float* __restrict__ bo,
           float* __restrict__ out_team,
           int n_teams) {
    extern __shared__ float smem[];
    float* Wos = smem;                      // 256*128 = 128 KB (half of Wo)
    float* xs  = smem + HIDDEN * H2;        // 64 KB

    const int tid  = threadIdx.x;
    const int c    = tid >> 5;
    const int lane = tid & 31;
    const int H    = blockIdx.y;            // 0 or 1

    {   // stage Wo[:, H*128 .. H*128+127]
        const float4* src = (const float4*)Wo;
        float4* dst = (float4*)Wos;
        for (int v = tid; v < 8192; v += NT) {
            int row = v >> 5;               // 32 float4 per smem row
            int cc  = v & 31;
            dst[v] = src[row * 64 + H * 32 + cc];
        }
    }

    const int colg = H * H2 + 8 * c;        // global col base for this warp
    const float4 boa = *(const float4*)&bo[colg];
    const float4 bob = *(const float4*)&bo[colg + 4];

    for (int base = blockIdx.x * 64; base < n_teams; base += gridDim.x * 64) {
        __syncthreads();
        stage_tile(xs, (const float4*)g_team_pre, base, n_teams, tid);
        __syncthreads();

        ull accF[4], accS[4];
        gemm_core(Wos, xs, c, lane, accF, accS);

        float2 f0 = upk2(accF[0]), s0 = upk2(accS[0]);
        float2 f1 = upk2(accF[1]), s1 = upk2(accS[1]);
        float2 f2 = upk2(accF[2]), s2 = upk2(accS[2]);
        float2 f3 = upk2(accF[3]), s3 = upk2(accS[3]);

        int ra = base + 2 * lane;
        int rb = ra + 1;
        if (ra < n_teams) {
            float4 o0, o1;
            o0.x = fmaxf(f0.x + boa.x, 0.f);
            o0.y = fmaxf(s0.y + boa.y, 0.f);
            o0.z = fmaxf(f1.x + boa.z, 0.f);
            o0.w = fmaxf(s1.y + boa.w, 0.f);
            o1.x = fmaxf(f2.x + bob.x, 0.f);
            o1.y = fmaxf(s2.y + bob.y, 0.f);
            o1.z = fmaxf(f3.x + bob.z, 0.f);
            o1.w = fmaxf(s3.y + bob.w, 0.f);
            float* dst = out_team + (size_t)ra * HIDDEN + colg;
            *(float4*)dst       = o0;
            *(float4*)(dst + 4) = o1;
        }
        if (rb < n_teams) {
            float4 o0, o1;
            o0.x = fmaxf(s0.x + boa.x, 0.f);
            o0.y = fmaxf(f0.y + boa.y, 0.f);
            o0.z = fmaxf(s1.x + boa.z, 0.f);
            o0.w = fmaxf(f1.y + boa.w, 0.f);
            o1.x = fmaxf(s2.x + bob.x, 0.f);
            o1.y = fmaxf(f2.y + bob.y, 0.f);
            o1.z = fmaxf(s3.x + bob.z, 0.f);
            o1.w = fmaxf(f3.y + bob.w, 0.f);
            float* dst = out_team + (size_t)rb * HIDDEN + colg;
            *(float4*)dst       = o0;
            *(float4*)(dst + 4) = o1;
        }
    }
}

// ---------------------------------------------------------------------------
extern "C" void kernel_launch(void* const* d_in, const int* in_sizes, int n_in,
                              void* d_out, int out_size) {
    const float* agent_h  = (const float*)d_in[0];
    const void*  team_idx = d_in[1];   // int32 or int64 -> detected on device
    const float* W1 = (const float*)d_in[3];
    const float* b1 = (const float*)d_in[4];
    const float* W2 = (const float*)d_in[5];
    const float* b2 = (const float*)d_in[6];
    const float* Wo = (const float*)d_in[7];
    const float* bo = (const float*)d_in[8];

    const int n_agents = in_sizes[0] / HIDDEN;
    const int n_teams  = (out_size - n_agents) / HIDDEN;

    float* out_team = (float*)d_out;
    float* out_attn = out_team + (size_t)n_teams * HIDDEN;

    const int SMEM_SCORES = (HIDDEN * H2 + HIDDEN * 64 + 16 * 64) * sizeof(float); // 200704
    const int SMEM_OUT    = (HIDDEN * H2 + HIDDEN * 64) * sizeof(float);           // 196608
    cudaFuncSetAttribute(k_scores, cudaFuncAttributeMaxDynamicSharedMemorySize,
                         SMEM_SCORES);
    cudaFuncSetAttribute(k_out, cudaFuncAttributeMaxDynamicSharedMemorySize,
                         SMEM_OUT);

    // dtype detect + CSR build
    const int nscan = (n_teams + 1023) / 1024;
    k_detect<<<1, 256>>>(team_idx, n_agents, n_teams);
    k_zero_counts<<<(n_teams + 255) / 256, 256>>>(n_teams);
    k_count<<<(n_agents + 255) / 256, 256>>>(team_idx, n_agents, n_teams);
    k_scan1<<<nscan, 1024>>>(n_teams);
    k_scan2<<<1, 128>>>(nscan);
    k_scan3<<<nscan, 1024>>>(n_teams);
    k_fill<<<(n_agents + 255) / 256, 256>>>(team_idx, n_agents, n_teams);

    // per-agent scores
    k_scores<<<148, NT, SMEM_SCORES>>>(agent_h, W1, b1, W2, b2, n_agents);

    // segment softmax + weighted pooling (also writes attn output)
    k_team<<<(n_teams + 7) / 8, 256>>>(agent_h, out_attn, n_teams);

    // output projection + relu
    dim3 og(74, 2, 1);
    k_out<<<og, NT, SMEM_OUT>>>(Wo, bo, out_team, n_teams);
}

// round 14
// speedup vs baseline: 1.9567x; 1.7091x over previous
#include <cuda_runtime.h>
#include <cuda_bf16.h>
#include <math_constants.h>

// ---------------------------------------------------------------------------
// GroupPooling via legacy mma.sync (HMMA) bf16 split GEMMs.
// scores = W2 . tanh(X@W1 + b1) + b2 ; segment softmax; weighted pool;
// out = relu(team_pre@Wo + bo).
// GEMM: A,B split to bf16 hi+lo; D = AhBh + AhBl + AlBh (fp32 accum).
// NOTE: tcgen05 is unavailable (harness lowers via compute_103, no 'a' feature);
// mma.sync.m16n8k16.bf16 is baseline PTX and compiles fine.
// ---------------------------------------------------------------------------

#define HIDDEN   256
#define H2       128
#define MAX_AGENTS 400000
#define MAX_TEAMS  100000

typedef unsigned int u32;
typedef __nv_bfloat16 bf16;

// ---- device scratch ---------------------------------------------------------
__device__ float g_scores[MAX_AGENTS];
__device__ int   g_counts[MAX_TEAMS];
__device__ int   g_offs[MAX_TEAMS + 1];
__device__ int   g_bsum[128];
__device__ int   g_order[MAX_AGENTS];
__device__ int   g_idx64;
__device__ float g_team_pre[(size_t)MAX_TEAMS * HIDDEN];

// ---- smem layout (bytes) ----------------------------------------------------
// vec area: [0,512) b1s/bos, [512,1024) w2s, [1024,2048) ps (2x128 f32)
#define OFF_VEC0 0
#define OFF_VEC1 512
#define OFF_PS   1024
#define OFF_AH   2048
#define SA       136                       // A row stride in bf16 (128+8 pad)
#define A_BYTES  (128 * SA * 2)            // 34816
#define OFF_AL   (OFF_AH + A_BYTES)
#define OFF_BH   (OFF_AL + A_BYTES)        // 71680
#define SB       264                       // B row stride in bf16 (256+8 pad)
#define B_BYTES  (128 * SB * 2)            // 67584
#define OFF_BL   (OFF_BH + B_BYTES)
#define SMEM_MMA (OFF_BL + B_BYTES)        // 206848

// ---------------------------------------------------------------------------
__device__ __forceinline__ void mma16816(float c[4], const u32 a[4],
                                         u32 b0, u32 b1) {
    asm volatile(
        "mma.sync.aligned.m16n8k16.row.col.f32.bf16.bf16.f32 "
        "{%0,%1,%2,%3}, {%4,%5,%6,%7}, {%8,%9}, {%0,%1,%2,%3};"
        : "+f"(c[0]), "+f"(c[1]), "+f"(c[2]), "+f"(c[3])
        : "r"(a[0]), "r"(a[1]), "r"(a[2]), "r"(a[3]), "r"(b0), "r"(b1));
}

// ---------------------------------------------------------------------------
// dtype detection + CSR build (proven)
// ---------------------------------------------------------------------------
__global__ void k_detect(const void* __restrict__ team_idx, int n_agents,
                         int n_teams) {
    __shared__ int ok_s;
    if (threadIdx.x == 0) ok_s = 1;
    __syncthreads();
    int K = n_agents < 1024 ? n_agents : 1024;
    const long long* p = (const long long*)team_idx;
    for (int i = threadIdx.x; i < K; i += blockDim.x) {
        long long v = p[i];
        if (v < 0 || v >= (long long)n_teams) ok_s = 0;
    }
    __syncthreads();
    if (threadIdx.x == 0) g_idx64 = ok_s;
}

__device__ __forceinline__ int load_team(const void* team_idx, int a,
                                         int n_teams) {
    int t;
    if (g_idx64) t = (int)((const long long*)team_idx)[a];
    else         t = ((const int*)team_idx)[a];
    if (t < 0) t = 0;
    if (t >= n_teams) t = n_teams - 1;
    return t;
}

__global__ void k_zero_counts(int n_teams) {
    int i = blockIdx.x * blockDim.x + threadIdx.x;
    if (i < n_teams) g_counts[i] = 0;
}

__global__ void k_count(const void* __restrict__ team_idx, int n_agents,
                        int n_teams) {
    int a = blockIdx.x * blockDim.x + threadIdx.x;
    if (a < n_agents) atomicAdd(&g_counts[load_team(team_idx, a, n_teams)], 1);
}

__global__ void k_scan1(int n_teams) {
    __shared__ int s[1024];
    int tid = threadIdx.x;
    int gid = blockIdx.x * 1024 + tid;
    int v = (gid < n_teams) ? g_counts[gid] : 0;
    s[tid] = v;
    __syncthreads();
    for (int off = 1; off < 1024; off <<= 1) {
        int t2 = (tid >= off) ? s[tid - off] : 0;
        __syncthreads();
        s[tid] += t2;
        __syncthreads();
    }
    if (gid < n_teams) g_offs[gid] = s[tid] - v;
    if (tid == 1023) g_bsum[blockIdx.x] = s[1023];
}

__global__ void k_scan2(int nblocks) {
    __shared__ int s[128];
    int tid = threadIdx.x;
    int v = (tid < nblocks) ? g_bsum[tid] : 0;
    s[tid] = v;
    __syncthreads();
    for (int off = 1; off < 128; off <<= 1) {
        int t2 = (tid >= off) ? s[tid - off] : 0;
        __syncthreads();
        s[tid] += t2;
        __syncthreads();
    }
    g_bsum[tid] = s[tid] - v;
}

__global__ void k_scan3(int n_teams) {
    int gid = blockIdx.x * 1024 + threadIdx.x;
    if (gid < n_teams) g_offs[gid] += g_bsum[blockIdx.x];
}

__global__ void k_fill(const void* __restrict__ team_idx, int n_agents,
                       int n_teams) {
    int a = blockIdx.x * blockDim.x + threadIdx.x;
    if (a < n_agents) {
        int t = load_team(team_idx, a, n_teams);
        int pos = atomicAdd(&g_offs[t], 1);
        g_order[pos] = a;
    }
}

// ---------------------------------------------------------------------------
// Staging helpers
// ---------------------------------------------------------------------------
__device__ __forceinline__ void split_bf16(float x, bf16& h, bf16& l) {
    h = __float2bfloat16(x);
    l = __float2bfloat16(x - __bfloat162float(h));
}

// B = W^T: B[n][k] = W[k][coloff+n], n<128, k<256, row stride SB.
__device__ __forceinline__ void stage_B(char* smem, const float* __restrict__ W,
                                        int ldw, int coloff, int tid) {
    bf16* Bh = (bf16*)(smem + OFF_BH);
    bf16* Bl = (bf16*)(smem + OFF_BL);
    for (int idx = tid; idx < 256 * 128; idx += 256) {
        int k = idx >> 7, n = idx & 127;
        bf16 h, l;
        split_bf16(W[k * ldw + coloff + n], h, l);
        Bh[n * SB + k] = h;
        Bl[n * SB + k] = l;
    }
}

// A chunk: rows base..base+127 of src[*,256], k cols [chunk*128,+128).
__device__ __forceinline__ void stage_A(char* smem, const float* __restrict__ src,
                                        int base, int n_rows, int chunk, int tid) {
    bf16* Ah = (bf16*)(smem + OFF_AH);
    bf16* Al = (bf16*)(smem + OFF_AL);
    const float4* s4 = (const float4*)src;
    for (int v = tid; v < 4096; v += 256) {
        int r = v >> 5, c4 = v & 31;
        int row = base + r;
        float4 x = (row < n_rows) ? s4[(size_t)row * 64 + chunk * 32 + c4]
                                  : make_float4(0.f, 0.f, 0.f, 0.f);
        bf16 h0, h1, h2, h3, l0, l1, l2, l3;
        split_bf16(x.x, h0, l0); split_bf16(x.y, h1, l1);
        split_bf16(x.z, h2, l2); split_bf16(x.w, h3, l3);
        int o = r * SA + 4 * c4;
        __nv_bfloat162 p;
        p.x = h0; p.y = h1; *(__nv_bfloat162*)(Ah + o)     = p;
        p.x = h2; p.y = h3; *(__nv_bfloat162*)(Ah + o + 2) = p;
        p.x = l0; p.y = l1; *(__nv_bfloat162*)(Al + o)     = p;
        p.x = l2; p.y = l3; *(__nv_bfloat162*)(Al + o + 2) = p;
    }
}

// One 128-k chunk of HMMA work: C[2][8][4] += A_chunk @ B[:, kbase..kbase+128)
__device__ __forceinline__ void gemm_chunk(float C[2][8][4], const char* smem,
                                           int wm, int wn, int lane, int kbase) {
    const bf16* Ah = (const bf16*)(smem + OFF_AH);
    const bf16* Al = (const bf16*)(smem + OFF_AL);
    const bf16* Bh = (const bf16*)(smem + OFF_BH);
    const bf16* Bl = (const bf16*)(smem + OFF_BL);
    const int qr = lane >> 2;
    const int qc = lane & 3;

    for (int s = 0; s < 8; s++) {
        int kc = s * 16;
        u32 ah[2][4], al[2][4];
#pragma unroll
        for (int mt = 0; mt < 2; mt++) {
            int r0 = wm * 32 + mt * 16 + qr;
            const bf16* pa = Ah + r0 * SA + kc + 2 * qc;
            ah[mt][0] = *(const u32*)pa;
            ah[mt][1] = *(const u32*)(pa + 8 * SA);
            ah[mt][2] = *(const u32*)(pa + 8);
            ah[mt][3] = *(const u32*)(pa + 8 * SA + 8);
            const bf16* pl = Al + r0 * SA + kc + 2 * qc;
            al[mt][0] = *(const u32*)pl;
            al[mt][1] = *(const u32*)(pl + 8 * SA);
            al[mt][2] = *(const u32*)(pl + 8);
            al[mt][3] = *(const u32*)(pl + 8 * SA + 8);
        }
#pragma unroll
        for (int nt = 0; nt < 8; nt++) {
            int n = wn * 64 + nt * 8 + qr;
            int kb = kbase + kc + 2 * qc;
            const bf16* pb = Bh + n * SB + kb;
            u32 bh0 = *(const u32*)pb;
            u32 bh1 = *(const u32*)(pb + 8);
            const bf16* pbl = Bl + n * SB + kb;
            u32 bl0 = *(const u32*)pbl;
            u32 bl1 = *(const u32*)(pbl + 8);
#pragma unroll
            for (int mt = 0; mt < 2; mt++) {
                mma16816(C[mt][nt], ah[mt], bh0, bh1);
                mma16816(C[mt][nt], ah[mt], bl0, bl1);
                mma16816(C[mt][nt], al[mt], bh0, bh1);
            }
        }
    }
}

// ---------------------------------------------------------------------------
// k_scores_mma: D = X_tile @ W1 (HMMA), epilogue tanh(D+b1).W2 + b2.
// ---------------------------------------------------------------------------
__global__ __launch_bounds__(256, 1)
void k_scores_mma(const float* __restrict__ X,
                  const float* __restrict__ W1,
                  const float* __restrict__ b1,
                  const float* __restrict__ W2,
                  const float* __restrict__ b2,
                  int n_agents) {
    extern __shared__ char smem[];
    float* b1s = (float*)(smem + OFF_VEC0);
    float* w2s = (float*)(smem + OFF_VEC1);
    float* ps  = (float*)(smem + OFF_PS);

    const int tid  = threadIdx.x;
    const int wid  = tid >> 5;
    const int lane = tid & 31;
    const int wm   = wid & 3;
    const int wn   = wid >> 2;
    const int qr   = lane >> 2;
    const int qc   = lane & 3;

    for (int i = tid; i < H2; i += 256) { b1s[i] = b1[i]; w2s[i] = W2[i]; }
    stage_B(smem, W1, H2, 0, tid);
    const float b2s = __ldg(b2);

    const int ntiles = (n_agents + 127) >> 7;
    for (int tile = blockIdx.x; tile < ntiles; tile += gridDim.x) {
        int base = tile << 7;
        float C[2][8][4];
#pragma unroll
        for (int mt = 0; mt < 2; mt++)
#pragma unroll
            for (int nt = 0; nt < 8; nt++)
#pragma unroll
                for (int j = 0; j < 4; j++) C[mt][nt][j] = 0.f;

#pragma unroll
        for (int chunk = 0; chunk < 2; chunk++) {
            __syncthreads();           // prior-iter readers done (A, ps)
            stage_A(smem, X, base, n_agents, chunk, tid);
            __syncthreads();
            gemm_chunk(C, smem, wm, wn, lane, chunk * 128);
        }

        // epilogue: per-row partial sum of tanh(c+b1)*w2 over this warp's cols
        float acc[2][2];
#pragma unroll
        for (int mt = 0; mt < 2; mt++) { acc[mt][0] = 0.f; acc[mt][1] = 0.f; }
#pragma unroll
        for (int nt = 0; nt < 8; nt++) {
            int c0 = wn * 64 + nt * 8 + 2 * qc;
            float bw0 = b1s[c0], bw1 = b1s[c0 + 1];
            float w0 = w2s[c0], w1 = w2s[c0 + 1];
#pragma unroll
            for (int mt = 0; mt < 2; mt++) {
                acc[mt][0] += tanhf(C[mt][nt][0] + bw0) * w0
                            + tanhf(C[mt][nt][1] + bw1) * w1;
                acc[mt][1] += tanhf(C[mt][nt][2] + bw0) * w0
                            + tanhf(C[mt][nt][3] + bw1) * w1;
            }
        }
#pragma unroll
        for (int mt = 0; mt < 2; mt++)
#pragma unroll
            for (int h = 0; h < 2; h++) {
                float v = acc[mt][h];
                v += __shfl_xor_sync(0xFFFFFFFFu, v, 1);
                v += __shfl_xor_sync(0xFFFFFFFFu, v, 2);
                acc[mt][h] = v;
            }
        if (qc == 0) {
#pragma unroll
            for (int mt = 0; mt < 2; mt++) {
                int rl = wm * 32 + mt * 16 + qr;
                ps[wn * 128 + rl]     = acc[mt][0];
                ps[wn * 128 + rl + 8] = acc[mt][1];
            }
        }
        __syncthreads();
        if (tid < 128) {
            int row = base + tid;
            if (row < n_agents)
                g_scores[row] = ps[tid] + ps[128 + tid] + b2s;
        }
    }
}

// ---------------------------------------------------------------------------
// k_team: one warp per team (proven)
// ---------------------------------------------------------------------------
__global__ void k_team(const float* __restrict__ agent_h,
                       float* __restrict__ out_attn,
                       int n_teams) {
    int t = blockIdx.x * 8 + (threadIdx.x >> 5);
    int lane = threadIdx.x & 31;
    if (t >= n_teams) return;

    int end = g_offs[t];
    int cnt = g_counts[t];
    int start = end - cnt;

    float m = -CUDART_INF_F;
    for (int b = 0; b < cnt; b += 32) {
        int i = b + lane;
        float s = (i < cnt) ? g_scores[g_order[start + i]] : -CUDART_INF_F;
        m = fmaxf(m, s);
    }
#pragma unroll
    for (int o = 16; o > 0; o >>= 1)
        m = fmaxf(m, __shfl_xor_sync(0xFFFFFFFFu, m, o));

    float esum = 0.f;
    for (int b = 0; b < cnt; b += 32) {
        int i = b + lane;
        if (i < cnt) {
            int a = g_order[start + i];
            float e = expf(g_scores[a] - m);
            g_scores[a] = e;
            esum += e;
        }
    }
#pragma unroll
    for (int o = 16; o > 0; o >>= 1)
        esum += __shfl_xor_sync(0xFFFFFFFFu, esum, o);
    __syncwarp();

    float inv = (cnt > 0) ? (1.f / esum) : 0.f;

    float4 acc0 = make_float4(0.f, 0.f, 0.f, 0.f);
    float4 acc1 = make_float4(0.f, 0.f, 0.f, 0.f);
    for (int mI = 0; mI < cnt; mI++) {
        int a = g_order[start + mI];
        float wgt = g_scores[a] * inv;
        if (lane == 0) out_attn[a] = wgt;
        const float4* row = (const float4*)(agent_h + (size_t)a * HIDDEN);
        float4 x0 = row[lane];
        float4 x1 = row[32 + lane];
        acc0.x += wgt * x0.x; acc0.y += wgt * x0.y;
        acc0.z += wgt * x0.z; acc0.w += wgt * x0.w;
        acc1.x += wgt * x1.x; acc1.y += wgt * x1.y;
        acc1.z += wgt * x1.z; acc1.w += wgt * x1.w;
    }
    float4* dst = (float4*)(g_team_pre + (size_t)t * HIDDEN);
    dst[lane]      = acc0;
    dst[32 + lane] = acc1;
}

// ---------------------------------------------------------------------------
// k_out_mma: out[:, H*128:+128] = relu(team_pre @ Wo_half + bo_half)
// ---------------------------------------------------------------------------
__global__ __launch_bounds__(256, 1)
void k_out_mma(const float* __restrict__ Wo,
               const float* __restrict__ bo,
               float* __restrict__ out_team,
               int n_teams) {
    extern __shared__ char smem[];
    float* bos = (float*)(smem + OFF_VEC0);

    const int tid  = threadIdx.x;
    const int wid  = tid >> 5;
    const int lane = tid & 31;
    const int wm   = wid & 3;
    const int wn   = wid >> 2;
    const int qr   = lane >> 2;
    const int qc   = lane & 3;
    const int H    = blockIdx.y;

    for (int i = tid; i < H2; i += 256) bos[i] = bo[H * H2 + i];
    stage_B(smem, Wo, HIDDEN, H * H2, tid);

    const int ntiles = (n_teams + 127) >> 7;
    for (int tile = blockIdx.x; tile < ntiles; tile += gridDim.x) {
        int base = tile << 7;
        float C[2][8][4];
#pragma unroll
        for (int mt = 0; mt < 2; mt++)
#pragma unroll
            for (int nt = 0; nt < 8; nt++)
#pragma unroll
                for (int j = 0; j < 4; j++) C[mt][nt][j] = 0.f;

#pragma unroll
        for (int chunk = 0; chunk < 2; chunk++) {
            __syncthreads();
            stage_A(smem, g_team_pre, base, n_teams, chunk, tid);
            __syncthreads();
            gemm_chunk(C, smem, wm, wn, lane, chunk * 128);
        }

        // epilogue: relu(c + bo) -> out
#pragma unroll
        for (int mt = 0; mt < 2; mt++) {
            int r0 = base + wm * 32 + mt * 16 + qr;
#pragma unroll
            for (int nt = 0; nt < 8; nt++) {
                int cl = wn * 64 + nt * 8 + 2 * qc;
                int cg = H * H2 + cl;
                float b0 = bos[cl], b1v = bos[cl + 1];
                if (r0 < n_teams) {
                    float2 o;
                    o.x = fmaxf(C[mt][nt][0] + b0, 0.f);
                    o.y = fmaxf(C[mt][nt][1] + b1v, 0.f);
                    *(float2*)(out_team + (size_t)r0 * HIDDEN + cg) = o;
                }
                if (r0 + 8 < n_teams) {
                    float2 o;
                    o.x = fmaxf(C[mt][nt][2] + b0, 0.f);
                    o.y = fmaxf(C[mt][nt][3] + b1v, 0.f);
                    *(float2*)(out_team + (size_t)(r0 + 8) * HIDDEN + cg) = o;
                }
            }
        }
    }
}

// ---------------------------------------------------------------------------
extern "C" void kernel_launch(void* const* d_in, const int* in_sizes, int n_in,
                              void* d_out, int out_size) {
    const float* agent_h  = (const float*)d_in[0];
    const void*  team_idx = d_in[1];
    const float* W1 = (const float*)d_in[3];
    const float* b1 = (const float*)d_in[4];
    const float* W2 = (const float*)d_in[5];
    const float* b2 = (const float*)d_in[6];
    const float* Wo = (const float*)d_in[7];
    const float* bo = (const float*)d_in[8];

    const int n_agents = in_sizes[0] / HIDDEN;
    const int n_teams  = (out_size - n_agents) / HIDDEN;

    float* out_team = (float*)d_out;
    float* out_attn = out_team + (size_t)n_teams * HIDDEN;

    cudaFuncSetAttribute(k_scores_mma,
                         cudaFuncAttributeMaxDynamicSharedMemorySize, SMEM_MMA);
    cudaFuncSetAttribute(k_out_mma,
                         cudaFuncAttributeMaxDynamicSharedMemorySize, SMEM_MMA);

    // dtype detect + CSR build
    const int nscan = (n_teams + 1023) / 1024;
    k_detect<<<1, 256>>>(team_idx, n_agents, n_teams);
    k_zero_counts<<<(n_teams + 255) / 256, 256>>>(n_teams);
    k_count<<<(n_agents + 255) / 256, 256>>>(team_idx, n_agents, n_teams);
    k_scan1<<<nscan, 1024>>>(n_teams);
    k_scan2<<<1, 128>>>(nscan);
    k_scan3<<<nscan, 1024>>>(n_teams);
    k_fill<<<(n_agents + 255) / 256, 256>>>(team_idx, n_agents, n_teams);

    // per-agent scores (HMMA GEMM + fused tanh/dot epilogue)
    k_scores_mma<<<148, 256, SMEM_MMA>>>(agent_h, W1, b1, W2, b2, n_agents);

    // segment softmax + weighted pooling
    k_team<<<(n_teams + 7) / 8, 256>>>(agent_h, out_attn, n_teams);

    // output projection + relu (HMMA GEMM), two column halves
    dim3 og(148, 2, 1);
    k_out_mma<<<og, 256, SMEM_MMA>>>(Wo, bo, out_team, n_teams);
}

// round 15
// speedup vs baseline: 2.3137x; 1.1825x over previous
#include <cuda_runtime.h>
#include <cuda_bf16.h>
#include <math_constants.h>

// ---------------------------------------------------------------------------
// GroupPooling via legacy mma.sync (HMMA) bf16 split GEMMs + ldmatrix.
// scores = W2 . tanh(X@W1 + b1) + b2 ; segment softmax; weighted pool;
// out = relu(team_pre@Wo + bo).
// GEMM: A,B split to bf16 hi+lo; D = AhBh + AhBl + AlBh (fp32 accum).
// tcgen05 unavailable (harness lowers via compute_103 virtual arch).
// ---------------------------------------------------------------------------

#define HIDDEN   256
#define H2       128
#define MAX_AGENTS 400000
#define MAX_TEAMS  100000
#define NT 512                 // 16 warps: 4m x 4n warp grid

typedef unsigned int u32;
typedef __nv_bfloat16 bf16;

// ---- device scratch ---------------------------------------------------------
__device__ float g_scores[MAX_AGENTS];
__device__ int   g_counts[MAX_TEAMS];
__device__ int   g_offs[MAX_TEAMS + 1];
__device__ int   g_bsum[128];
__device__ int   g_order[MAX_AGENTS];
__device__ int   g_idx64;
__device__ float g_team_pre[(size_t)MAX_TEAMS * HIDDEN];

// ---- smem layout (bytes) ----------------------------------------------------
#define OFF_VEC0 0                          // 128 f32 (b1 / bo)
#define OFF_VEC1 512                        // 128 f32 (w2)
#define OFF_PS   1024                       // 4*128 f32 partials
#define OFF_AH   3072
#define SA       136                        // A row stride in bf16 (128+8)
#define A_BYTES  (128 * SA * 2)             // 34816
#define OFF_AL   (OFF_AH + A_BYTES)
#define OFF_BH   (OFF_AL + A_BYTES)
#define SB       264                        // B row stride in bf16 (256+8)
#define B_BYTES  (128 * SB * 2)             // 67584
#define OFF_BL   (OFF_BH + B_BYTES)
#define SMEM_MMA (OFF_BL + B_BYTES)         // 207872

// ---------------------------------------------------------------------------
__device__ __forceinline__ u32 smem_u32(const void* p) {
    u32 a;
    asm("{ .reg .u64 t; cvta.to.shared.u64 t, %1; cvt.u32.u64 %0, t; }"
        : "=r"(a) : "l"(p));
    return a;
}

__device__ __forceinline__ void mma16816(float c[4], const u32 a[4],
                                         u32 b0, u32 b1) {
    asm volatile(
        "mma.sync.aligned.m16n8k16.row.col.f32.bf16.bf16.f32 "
        "{%0,%1,%2,%3}, {%4,%5,%6,%7}, {%8,%9}, {%0,%1,%2,%3};"
        : "+f"(c[0]), "+f"(c[1]), "+f"(c[2]), "+f"(c[3])
        : "r"(a[0]), "r"(a[1]), "r"(a[2]), "r"(a[3]), "r"(b0), "r"(b1));
}

#define LDM4(r, addr) \
    asm volatile("ldmatrix.sync.aligned.m8n8.x4.shared.b16 {%0,%1,%2,%3}, [%4];" \
                 : "=r"((r)[0]), "=r"((r)[1]), "=r"((r)[2]), "=r"((r)[3]) \
                 : "r"(addr))

// ---------------------------------------------------------------------------
// dtype detection + CSR build (proven)
// ---------------------------------------------------------------------------
__global__ void k_detect(const void* __restrict__ team_idx, int n_agents,
                         int n_teams) {
    __shared__ int ok_s;
    if (threadIdx.x == 0) ok_s = 1;
    __syncthreads();
    int K = n_agents < 1024 ? n_agents : 1024;
    const long long* p = (const long long*)team_idx;
    for (int i = threadIdx.x; i < K; i += blockDim.x) {
        long long v = p[i];
        if (v < 0 || v >= (long long)n_teams) ok_s = 0;
    }
    __syncthreads();
    if (threadIdx.x == 0) g_idx64 = ok_s;
}

__device__ __forceinline__ int load_team(const void* team_idx, int a,
                                         int n_teams) {
    int t;
    if (g_idx64) t = (int)((const long long*)team_idx)[a];
    else         t = ((const int*)team_idx)[a];
    if (t < 0) t = 0;
    if (t >= n_teams) t = n_teams - 1;
    return t;
}

__global__ void k_zero_counts(int n_teams) {
    int i = blockIdx.x * blockDim.x + threadIdx.x;
    if (i < n_teams) g_counts[i] = 0;
}

__global__ void k_count(const void* __restrict__ team_idx, int n_agents,
                        int n_teams) {
    int a = blockIdx.x * blockDim.x + threadIdx.x;
    if (a < n_agents) atomicAdd(&g_counts[load_team(team_idx, a, n_teams)], 1);
}

__global__ void k_scan1(int n_teams) {
    __shared__ int s[1024];
    int tid = threadIdx.x;
    int gid = blockIdx.x * 1024 + tid;
    int v = (gid < n_teams) ? g_counts[gid] : 0;
    s[tid] = v;
    __syncthreads();
    for (int off = 1; off < 1024; off <<= 1) {
        int t2 = (tid >= off) ? s[tid - off] : 0;
        __syncthreads();
        s[tid] += t2;
        __syncthreads();
    }
    if (gid < n_teams) g_offs[gid] = s[tid] - v;
    if (tid == 1023) g_bsum[blockIdx.x] = s[1023];
}

__global__ void k_scan2(int nblocks) {
    __shared__ int s[128];
    int tid = threadIdx.x;
    int v = (tid < nblocks) ? g_bsum[tid] : 0;
    s[tid] = v;
    __syncthreads();
    for (int off = 1; off < 128; off <<= 1) {
        int t2 = (tid >= off) ? s[tid - off] : 0;
        __syncthreads();
        s[tid] += t2;
        __syncthreads();
    }
    g_bsum[tid] = s[tid] - v;
}

__global__ void k_scan3(int n_teams) {
    int gid = blockIdx.x * 1024 + threadIdx.x;
    if (gid < n_teams) g_offs[gid] += g_bsum[blockIdx.x];
}

__global__ void k_fill(const void* __restrict__ team_idx, int n_agents,
                       int n_teams) {
    int a = blockIdx.x * blockDim.x + threadIdx.x;
    if (a < n_agents) {
        int t = load_team(team_idx, a, n_teams);
        int pos = atomicAdd(&g_offs[t], 1);
        g_order[pos] = a;
    }
}

// ---------------------------------------------------------------------------
// Staging helpers
// ---------------------------------------------------------------------------
__device__ __forceinline__ void split_bf16(float x, bf16& h, bf16& l) {
    h = __float2bfloat16(x);
    l = __float2bfloat16(x - __bfloat162float(h));
}

// B = W^T: B[n][k] = W[k][coloff+n], n<128, k<256, row stride SB.
__device__ __forceinline__ void stage_B(char* smem, const float* __restrict__ W,
                                        int ldw, int coloff, int tid) {
    bf16* Bh = (bf16*)(smem + OFF_BH);
    bf16* Bl = (bf16*)(smem + OFF_BL);
    for (int idx = tid; idx < 256 * 128; idx += NT) {
        int k = idx >> 7, n = idx & 127;
        bf16 h, l;
        split_bf16(W[k * ldw + coloff + n], h, l);
        Bh[n * SB + k] = h;
        Bl[n * SB + k] = l;
    }
}

// Convert prefetched registers -> A smem (hi/lo), 8 float4 per thread.
__device__ __forceinline__ void store_A(char* smem, const float4 v[8], int tid) {
    bf16* Ah = (bf16*)(smem + OFF_AH);
    bf16* Al = (bf16*)(smem + OFF_AL);
#pragma unroll
    for (int i = 0; i < 8; i++) {
        int idx = tid + i * NT;                 // 0..4095
        int r = idx >> 5, c4 = idx & 31;
        bf16 h0, h1, h2, h3, l0, l1, l2, l3;
        split_bf16(v[i].x, h0, l0); split_bf16(v[i].y, h1, l1);
        split_bf16(v[i].z, h2, l2); split_bf16(v[i].w, h3, l3);
        int o = r * SA + 4 * c4;
        __nv_bfloat162 p;
        p.x = h0; p.y = h1; *(__nv_bfloat162*)(Ah + o)     = p;
        p.x = h2; p.y = h3; *(__nv_bfloat162*)(Ah + o + 2) = p;
        p.x = l0; p.y = l1; *(__nv_bfloat162*)(Al + o)     = p;
        p.x = l2; p.y = l3; *(__nv_bfloat162*)(Al + o + 2) = p;
    }
}

__device__ __forceinline__ void prefetch_A(float4 v[8], const float* __restrict__ src,
                                           int base, int n_rows, int chunk, int tid) {
    const float4* s4 = (const float4*)src;
#pragma unroll
    for (int i = 0; i < 8; i++) {
        int idx = tid + i * NT;
        int r = idx >> 5, c4 = idx & 31;
        int row = base + r;
        v[i] = (row < n_rows) ? s4[(size_t)row * 64 + chunk * 32 + c4]
                              : make_float4(0.f, 0.f, 0.f, 0.f);
    }
}

// ---------------------------------------------------------------------------
// HMMA core: one 128-k chunk. Warp tile 32m x 32n: mt in {0,1} (16 rows),
// nt in {0..3} (8 cols). Fragments via ldmatrix.x4.
// ---------------------------------------------------------------------------
__device__ __forceinline__ void gemm_chunk(float C[2][4][4],
                                           const u32 aah[2], const u32 aal[2],
                                           const u32 bbh[2], const u32 bbl[2],
                                           int kbase) {
#pragma unroll
    for (int s = 0; s < 8; s++) {
        int koffA = s * 32;                    // 16 elems * 2B
        int koffB = (kbase + s * 16) * 2;
        u32 ah0[4], ah1[4], al0[4], al1[4];
        u32 bh0[4], bh1[4], bl0[4], bl1[4];
        LDM4(ah0, aah[0] + koffA);
        LDM4(ah1, aah[1] + koffA);
        LDM4(al0, aal[0] + koffA);
        LDM4(al1, aal[1] + koffA);
        LDM4(bh0, bbh[0] + koffB);
        LDM4(bh1, bbh[1] + koffB);
        LDM4(bl0, bbl[0] + koffB);
        LDM4(bl1, bbl[1] + koffB);
        // nt0: b0=g0[0], b1=g0[2]; nt1: g0[1], g0[3]; nt2: g1[0], g1[2]; nt3: g1[1], g1[3]
        mma16816(C[0][0], ah0, bh0[0], bh0[2]);
        mma16816(C[0][1], ah0, bh0[1], bh0[3]);
        mma16816(C[0][2], ah0, bh1[0], bh1[2]);
        mma16816(C[0][3], ah0, bh1[1], bh1[3]);
        mma16816(C[1][0], ah1, bh0[0], bh0[2]);
        mma16816(C[1][1], ah1, bh0[1], bh0[3]);
        mma16816(C[1][2], ah1, bh1[0], bh1[2]);
        mma16816(C[1][3], ah1, bh1[1], bh1[3]);

        mma16816(C[0][0], ah0, bl0[0], bl0[2]);
        mma16816(C[0][1], ah0, bl0[1], bl0[3]);
        mma16816(C[0][2], ah0, bl1[0], bl1[2]);
        mma16816(C[0][3], ah0, bl1[1], bl1[3]);
        mma16816(C[1][0], ah1, bl0[0], bl0[2]);
        mma16816(C[1][1], ah1, bl0[1], bl0[3]);
        mma16816(C[1][2], ah1, bl1[0], bl1[2]);
        mma16816(C[1][3], ah1, bl1[1], bl1[3]);

        mma16816(C[0][0], al0, bh0[0], bh0[2]);
        mma16816(C[0][1], al0, bh0[1], bh0[3]);
        mma16816(C[0][2], al0, bh1[0], bh1[2]);
        mma16816(C[0][3], al0, bh1[1], bh1[3]);
        mma16816(C[1][0], al1, bh0[0], bh0[2]);
        mma16816(C[1][1], al1, bh0[1], bh0[3]);
        mma16816(C[1][2], al1, bh1[0], bh1[2]);
        mma16816(C[1][3], al1, bh1[1], bh1[3]);
    }
}

// Compute per-lane ldmatrix base addresses.
__device__ __forceinline__ void frag_bases(u32 sb, int wm, int wn, int lane,
                                           u32 aah[2], u32 aal[2],
                                           u32 bbh[2], u32 bbl[2]) {
    int ar = lane & 15;
    int ak = (lane >> 4) * 16;                 // byte offset for k+8 half
#pragma unroll
    for (int mt = 0; mt < 2; mt++) {
        aah[mt] = sb + OFF_AH + (u32)((wm * 32 + mt * 16 + ar) * (SA * 2)) + ak;
        aal[mt] = aah[mt] + (OFF_AL - OFF_AH);
    }
#pragma unroll
    for (int g = 0; g < 2; g++) {
        bbh[g] = sb + OFF_BH + (u32)((wn * 32 + g * 16 + ar) * (SB * 2)) + ak;
        bbl[g] = bbh[g] + (OFF_BL - OFF_BH);
    }
}

// ---------------------------------------------------------------------------
// k_scores_mma: D = X_tile @ W1 (HMMA), epilogue tanh(D+b1).W2 + b2.
// ---------------------------------------------------------------------------
__global__ __launch_bounds__(NT, 1)
void k_scores_mma(const float* __restrict__ X,
                  const float* __restrict__ W1,
                  const float* __restrict__ b1,
                  const float* __restrict__ W2,
                  const float* __restrict__ b2,
                  int n_agents) {
    extern __shared__ char smem[];
    float* b1s = (float*)(smem + OFF_VEC0);
    float* w2s = (float*)(smem + OFF_VEC1);
    float* ps  = (float*)(smem + OFF_PS);

    const int tid  = threadIdx.x;
    const int wid  = tid >> 5;
    const int lane = tid & 31;
    const int wm   = wid & 3;
    const int wn   = wid >> 2;
    const int qr   = lane >> 2;
    const int qc   = lane & 3;
    const u32 sb   = smem_u32(smem);

    u32 aah[2], aal[2], bbh[2], bbl[2];
    frag_bases(sb, wm, wn, lane, aah, aal, bbh, bbl);

    for (int i = tid; i < H2; i += NT) { b1s[i] = b1[i]; w2s[i] = W2[i]; }
    stage_B(smem, W1, H2, 0, tid);
    const float b2s = __ldg(b2);

    const int ntiles = (n_agents + 127) >> 7;
    for (int tile = blockIdx.x; tile < ntiles; tile += gridDim.x) {
        int base = tile << 7;
        float C[2][4][4];
#pragma unroll
        for (int mt = 0; mt < 2; mt++)
#pragma unroll
            for (int nt = 0; nt < 4; nt++)
#pragma unroll
                for (int j = 0; j < 4; j++) C[mt][nt][j] = 0.f;

#pragma unroll
        for (int chunk = 0; chunk < 2; chunk++) {
            float4 v[8];
            prefetch_A(v, X, base, n_agents, chunk, tid);  // overlap w/ prev MMA
            __syncthreads();           // prior readers of A / ps done
            store_A(smem, v, tid);
            __syncthreads();
            gemm_chunk(C, aah, aal, bbh, bbl, chunk * 128);
        }

        // epilogue: per-row partial of tanh(c+b1)*w2 over this warp's 32 cols
        float acc[2][2];
        acc[0][0] = acc[0][1] = acc[1][0] = acc[1][1] = 0.f;
#pragma unroll
        for (int nt = 0; nt < 4; nt++) {
            int c0 = wn * 32 + nt * 8 + 2 * qc;
            float bw0 = b1s[c0], bw1 = b1s[c0 + 1];
            float w0 = w2s[c0], w1 = w2s[c0 + 1];
#pragma unroll
            for (int mt = 0; mt < 2; mt++) {
                acc[mt][0] += tanhf(C[mt][nt][0] + bw0) * w0
                            + tanhf(C[mt][nt][1] + bw1) * w1;
                acc[mt][1] += tanhf(C[mt][nt][2] + bw0) * w0
                            + tanhf(C[mt][nt][3] + bw1) * w1;
            }
        }
#pragma unroll
        for (int mt = 0; mt < 2; mt++)
#pragma unroll
            for (int h = 0; h < 2; h++) {
                float v2 = acc[mt][h];
                v2 += __shfl_xor_sync(0xFFFFFFFFu, v2, 1);
                v2 += __shfl_xor_sync(0xFFFFFFFFu, v2, 2);
                acc[mt][h] = v2;
            }
        if (qc == 0) {
#pragma unroll
            for (int mt = 0; mt < 2; mt++) {
                int rl = wm * 32 + mt * 16 + qr;
                ps[wn * 128 + rl]     = acc[mt][0];
                ps[wn * 128 + rl + 8] = acc[mt][1];
            }
        }
        __syncthreads();
        if (tid < 128) {
            int row = base + tid;
            if (row < n_agents)
                g_scores[row] = ps[tid] + ps[128 + tid] + ps[256 + tid]
                              + ps[384 + tid] + b2s;
        }
    }
}

// ---------------------------------------------------------------------------
// k_team: one warp per team (proven)
// ---------------------------------------------------------------------------
__global__ void k_team(const float* __restrict__ agent_h,
                       float* __restrict__ out_attn,
                       int n_teams) {
    int t = blockIdx.x * 8 + (threadIdx.x >> 5);
    int lane = threadIdx.x & 31;
    if (t >= n_teams) return;

    int end = g_offs[t];
    int cnt = g_counts[t];
    int start = end - cnt;

    float m = -CUDART_INF_F;
    for (int b = 0; b < cnt; b += 32) {
        int i = b + lane;
        float s = (i < cnt) ? g_scores[g_order[start + i]] : -CUDART_INF_F;
        m = fmaxf(m, s);
    }
#pragma unroll
    for (int o = 16; o > 0; o >>= 1)
        m = fmaxf(m, __shfl_xor_sync(0xFFFFFFFFu, m, o));

    float esum = 0.f;
    for (int b = 0; b < cnt; b += 32) {
        int i = b + lane;
        if (i < cnt) {
            int a = g_order[start + i];
            float e = expf(g_scores[a] - m);
            g_scores[a] = e;
            esum += e;
        }
    }
#pragma unroll
    for (int o = 16; o > 0; o >>= 1)
        esum += __shfl_xor_sync(0xFFFFFFFFu, esum, o);
    __syncwarp();

    float inv = (cnt > 0) ? (1.f / esum) : 0.f;

    float4 acc0 = make_float4(0.f, 0.f, 0.f, 0.f);
    float4 acc1 = make_float4(0.f, 0.f, 0.f, 0.f);
    for (int mI = 0; mI < cnt; mI++) {
        int a = g_order[start + mI];
        float wgt = g_scores[a] * inv;
        if (lane == 0) out_attn[a] = wgt;
        const float4* row = (const float4*)(agent_h + (size_t)a * HIDDEN);
        float4 x0 = row[lane];
        float4 x1 = row[32 + lane];
        acc0.x += wgt * x0.x; acc0.y += wgt * x0.y;
        acc0.z += wgt * x0.z; acc0.w += wgt * x0.w;
        acc1.x += wgt * x1.x; acc1.y += wgt * x1.y;
        acc1.z += wgt * x1.z; acc1.w += wgt * x1.w;
    }
    float4* dst = (float4*)(g_team_pre + (size_t)t * HIDDEN);
    dst[lane]      = acc0;
    dst[32 + lane] = acc1;
}

// ---------------------------------------------------------------------------
// k_out_mma: out[:, H*128:+128] = relu(team_pre @ Wo_half + bo_half)
// ---------------------------------------------------------------------------
__global__ __launch_bounds__(NT, 1)
void k_out_mma(const float* __restrict__ Wo,
               const float* __restrict__ bo,
               float* __restrict__ out_team,
               int n_teams) {
    extern __shared__ char smem[];
    float* bos = (float*)(smem + OFF_VEC0);

    const int tid  = threadIdx.x;
    const int wid  = tid >> 5;
    const int lane = tid & 31;
    const int wm   = wid & 3;
    const int wn   = wid >> 2;
    const int qr   = lane >> 2;
    const int qc   = lane & 3;
    const int H    = blockIdx.y;
    const u32 sb   = smem_u32(smem);

    u32 aah[2], aal[2], bbh[2], bbl[2];
    frag_bases(sb, wm, wn, lane, aah, aal, bbh, bbl);

    for (int i = tid; i < H2; i += NT) bos[i] = bo[H * H2 + i];
    stage_B(smem, Wo, HIDDEN, H * H2, tid);

    const int ntiles = (n_teams + 127) >> 7;
    for (int tile = blockIdx.x; tile < ntiles; tile += gridDim.x) {
        int base = tile << 7;
        float C[2][4][4];
#pragma unroll
        for (int mt = 0; mt < 2; mt++)
#pragma unroll
            for (int nt = 0; nt < 4; nt++)
#pragma unroll
                for (int j = 0; j < 4; j++) C[mt][nt][j] = 0.f;

#pragma unroll
        for (int chunk = 0; chunk < 2; chunk++) {
            float4 v[8];
            prefetch_A(v, g_team_pre, base, n_teams, chunk, tid);
            __syncthreads();
            store_A(smem, v, tid);
            __syncthreads();
            gemm_chunk(C, aah, aal, bbh, bbl, chunk * 128);
        }

        // epilogue: relu(c + bo) -> out
#pragma unroll
        for (int mt = 0; mt < 2; mt++) {
            int r0 = base + wm * 32 + mt * 16 + qr;
#pragma unroll
            for (int nt = 0; nt < 4; nt++) {
                int cl = wn * 32 + nt * 8 + 2 * qc;
                int cg = H * H2 + cl;
                float b0 = bos[cl], b1v = bos[cl + 1];
                if (r0 < n_teams) {
                    float2 o;
                    o.x = fmaxf(C[mt][nt][0] + b0, 0.f);
                    o.y = fmaxf(C[mt][nt][1] + b1v, 0.f);
                    *(float2*)(out_team + (size_t)r0 * HIDDEN + cg) = o;
                }
                if (r0 + 8 < n_teams) {
                    float2 o;
                    o.x = fmaxf(C[mt][nt][2] + b0, 0.f);
                    o.y = fmaxf(C[mt][nt][3] + b1v, 0.f);
                    *(float2*)(out_team + (size_t)(r0 + 8) * HIDDEN + cg) = o;
                }
            }
        }
    }
}

// ---------------------------------------------------------------------------
extern "C" void kernel_launch(void* const* d_in, const int* in_sizes, int n_in,
                              void* d_out, int out_size) {
    const float* agent_h  = (const float*)d_in[0];
    const void*  team_idx = d_in[1];
    const float* W1 = (const float*)d_in[3];
    const float* b1 = (const float*)d_in[4];
    const float* W2 = (const float*)d_in[5];
    const float* b2 = (const float*)d_in[6];
    const float* Wo = (const float*)d_in[7];
    const float* bo = (const float*)d_in[8];

    const int n_agents = in_sizes[0] / HIDDEN;
    const int n_teams  = (out_size - n_agents) / HIDDEN;

    float* out_team = (float*)d_out;
    float* out_attn = out_team + (size_t)n_teams * HIDDEN;

    cudaFuncSetAttribute(k_scores_mma,
                         cudaFuncAttributeMaxDynamicSharedMemorySize, SMEM_MMA);
    cudaFuncSetAttribute(k_out_mma,
                         cudaFuncAttributeMaxDynamicSharedMemorySize, SMEM_MMA);

    // dtype detect + CSR build
    const int nscan = (n_teams + 1023) / 1024;
    k_detect<<<1, 256>>>(team_idx, n_agents, n_teams);
    k_zero_counts<<<(n_teams + 255) / 256, 256>>>(n_teams);
    k_count<<<(n_agents + 255) / 256, 256>>>(team_idx, n_agents, n_teams);
    k_scan1<<<nscan, 1024>>>(n_teams);
    k_scan2<<<1, 128>>>(nscan);
    k_scan3<<<nscan, 1024>>>(n_teams);
    k_fill<<<(n_agents + 255) / 256, 256>>>(team_idx, n_agents, n_teams);

    // per-agent scores (HMMA GEMM + fused tanh/dot epilogue)
    k_scores_mma<<<148, NT, SMEM_MMA>>>(agent_h, W1, b1, W2, b2, n_agents);

    // segment softmax + weighted pooling
    k_team<<<(n_teams + 7) / 8, 256>>>(agent_h, out_attn, n_teams);

    // output projection + relu (HMMA GEMM), two column halves
    dim3 og(148, 2, 1);
    k_out_mma<<<og, NT, SMEM_MMA>>>(Wo, bo, out_team, n_teams);
}

// round 16
// speedup vs baseline: 2.4611x; 1.0637x over previous
#include <cuda_runtime.h>
#include <cuda_bf16.h>
#include <math_constants.h>

// ---------------------------------------------------------------------------
// GroupPooling via legacy mma.sync (HMMA) bf16 split GEMMs + ldmatrix.
// scores = W2 . tanh(X@W1 + b1) + b2 ; segment softmax; weighted pool;
// out = relu(team_pre@Wo + bo).
// GEMM: A,B split to bf16 hi+lo; D = AhBh + AhBl + AlBh (fp32 accum).
// A split uses truncation (PRMT hi-pack) for cheap staging.
// CSR build runs on a forked stream, overlapped with the scores GEMM.
// tcgen05 unavailable (harness lowers via compute_103 virtual arch).
// ---------------------------------------------------------------------------

#define HIDDEN   256
#define H2       128
#define MAX_AGENTS 400000
#define MAX_TEAMS  100000
#define NT 512                 // 16 warps: 4m x 4n warp grid

typedef unsigned int u32;
typedef unsigned long long ull;
typedef __nv_bfloat16 bf16;

// ---- device scratch ---------------------------------------------------------
__device__ float g_scores[MAX_AGENTS];
__device__ int   g_counts[MAX_TEAMS];
__device__ int   g_offs[MAX_TEAMS + 1];
__device__ int   g_bsum[128];
__device__ int   g_order[MAX_AGENTS];
__device__ int   g_idx64;
__device__ float g_team_pre[(size_t)MAX_TEAMS * HIDDEN];

// ---- smem layout (bytes) ----------------------------------------------------
#define OFF_VEC0 0                          // 128 f32 (b1 / bo)
#define OFF_VEC1 512                        // 128 f32 (w2)
#define OFF_PS   1024                       // 4*128 f32 partials
#define OFF_AH   3072
#define SA       136                        // A row stride in bf16 (128+8)
#define A_BYTES  (128 * SA * 2)             // 34816
#define OFF_AL   (OFF_AH + A_BYTES)
#define OFF_BH   (OFF_AL + A_BYTES)
#define SB       264                        // B row stride in bf16 (256+8)
#define B_BYTES  (128 * SB * 2)             // 67584
#define OFF_BL   (OFF_BH + B_BYTES)
#define SMEM_MMA (OFF_BL + B_BYTES)         // 207872

// ---------------------------------------------------------------------------
__device__ __forceinline__ u32 smem_u32(const void* p) {
    u32 a;
    asm("{ .reg .u64 t; cvta.to.shared.u64 t, %1; cvt.u32.u64 %0, t; }"
        : "=r"(a) : "l"(p));
    return a;
}

__device__ __forceinline__ void mma16816(float c[4], const u32 a[4],
                                         u32 b0, u32 b1) {
    asm volatile(
        "mma.sync.aligned.m16n8k16.row.col.f32.bf16.bf16.f32 "
        "{%0,%1,%2,%3}, {%4,%5,%6,%7}, {%8,%9}, {%0,%1,%2,%3};"
        : "+f"(c[0]), "+f"(c[1]), "+f"(c[2]), "+f"(c[3])
        : "r"(a[0]), "r"(a[1]), "r"(a[2]), "r"(a[3]), "r"(b0), "r"(b1));
}

#define LDM4(r, addr) \
    asm volatile("ldmatrix.sync.aligned.m8n8.x4.shared.b16 {%0,%1,%2,%3}, [%4];" \
                 : "=r"((r)[0]), "=r"((r)[1]), "=r"((r)[2]), "=r"((r)[3]) \
                 : "r"(addr))

// hi-pack: {lo16 = a[31:16], hi16 = b[31:16]} (truncated bf16 pair)
__device__ __forceinline__ u32 prmt_hi(u32 a, u32 b) {
    u32 r;
    asm("prmt.b32 %0, %1, %2, 0x7632;" : "=r"(r) : "r"(a), "r"(b));
    return r;
}
// pack two f32 -> bf16x2 {lo, hi} with round-to-nearest
__device__ __forceinline__ u32 pack_bf16_rn(float lo, float hi) {
    u32 r;
    asm("cvt.rn.bf16x2.f32 %0, %1, %2;" : "=r"(r) : "f"(hi), "f"(lo));
    return r;
}

// ---------------------------------------------------------------------------
// dtype detection + CSR build
// ---------------------------------------------------------------------------
__global__ void k_detect(const void* __restrict__ team_idx, int n_agents,
                         int n_teams) {
    __shared__ int ok_s;
    if (threadIdx.x == 0) ok_s = 1;
    __syncthreads();
    int K = n_agents < 1024 ? n_agents : 1024;
    const long long* p = (const long long*)team_idx;
    for (int i = threadIdx.x; i < K; i += blockDim.x) {
        long long v = p[i];
        if (v < 0 || v >= (long long)n_teams) ok_s = 0;
    }
    __syncthreads();
    if (threadIdx.x == 0) g_idx64 = ok_s;
}

__device__ __forceinline__ int load_team(const void* team_idx, int a,
                                         int n_teams) {
    int t;
    if (g_idx64) t = (int)((const long long*)team_idx)[a];
    else         t = ((const int*)team_idx)[a];
    if (t < 0) t = 0;
    if (t >= n_teams) t = n_teams - 1;
    return t;
}

__global__ void k_zero_counts(int n_teams) {
    int i = blockIdx.x * blockDim.x + threadIdx.x;
    if (i < n_teams) g_counts[i] = 0;
}

__global__ void k_count(const void* __restrict__ team_idx, int n_agents,
                        int n_teams) {
    int a = blockIdx.x * blockDim.x + threadIdx.x;
    if (a < n_agents) atomicAdd(&g_counts[load_team(team_idx, a, n_teams)], 1);
}

__global__ void k_scan1(int n_teams) {
    __shared__ int s[1024];
    int tid = threadIdx.x;
    int gid = blockIdx.x * 1024 + tid;
    int v = (gid < n_teams) ? g_counts[gid] : 0;
    s[tid] = v;
    __syncthreads();
    for (int off = 1; off < 1024; off <<= 1) {
        int t2 = (tid >= off) ? s[tid - off] : 0;
        __syncthreads();
        s[tid] += t2;
        __syncthreads();
    }
    if (gid < n_teams) g_offs[gid] = s[tid] - v;
    if (tid == 1023) g_bsum[blockIdx.x] = s[1023];
}

__global__ void k_scan2(int nblocks) {
    __shared__ int s[128];
    int tid = threadIdx.x;
    int v = (tid < nblocks) ? g_bsum[tid] : 0;
    s[tid] = v;
    __syncthreads();
    for (int off = 1; off < 128; off <<= 1) {
        int t2 = (tid >= off) ? s[tid - off] : 0;
        __syncthreads();
        s[tid] += t2;
        __syncthreads();
    }
    g_bsum[tid] = s[tid] - v;
}

__global__ void k_scan3(int n_teams) {
    int gid = blockIdx.x * 1024 + threadIdx.x;
    if (gid < n_teams) g_offs[gid] += g_bsum[blockIdx.x];
}

__global__ void k_fill(const void* __restrict__ team_idx, int n_agents,
                       int n_teams) {
    int a = blockIdx.x * blockDim.x + threadIdx.x;
    if (a < n_agents) {
        int t = load_team(team_idx, a, n_teams);
        int pos = atomicAdd(&g_offs[t], 1);
        g_order[pos] = a;
    }
}

// ---------------------------------------------------------------------------
// Staging helpers
// ---------------------------------------------------------------------------
__device__ __forceinline__ void split_bf16(float x, bf16& h, bf16& l) {
    h = __float2bfloat16(x);
    l = __float2bfloat16(x - __bfloat162float(h));
}

// B = W^T: B[n][k] = W[k][coloff+n], n<128, k<256, row stride SB. RN split.
__device__ __forceinline__ void stage_B(char* smem, const float* __restrict__ W,
                                        int ldw, int coloff, int tid) {
    bf16* Bh = (bf16*)(smem + OFF_BH);
    bf16* Bl = (bf16*)(smem + OFF_BL);
    for (int idx = tid; idx < 256 * 128; idx += NT) {
        int k = idx >> 7, n = idx & 127;
        bf16 h, l;
        split_bf16(W[k * ldw + coloff + n], h, l);
        Bh[n * SB + k] = h;
        Bl[n * SB + k] = l;
    }
}

__device__ __forceinline__ void prefetch_A(float4 v[8], const float* __restrict__ src,
                                           int base, int n_rows, int chunk, int tid) {
    const float4* s4 = (const float4*)src;
#pragma unroll
    for (int i = 0; i < 8; i++) {
        int idx = tid + i * NT;
        int r = idx >> 5, c4 = idx & 31;
        int row = base + r;
        v[i] = (row < n_rows) ? s4[(size_t)row * 64 + chunk * 32 + c4]
                              : make_float4(0.f, 0.f, 0.f, 0.f);
    }
}

// Truncation split + STS.64: h = x with low mantissa bits dropped (PRMT),
// l = rn_bf16(x - h). Dropped AlBl term ~2^-17.
__device__ __forceinline__ void store_A(char* smem, const float4 v[8], int tid) {
#pragma unroll
    for (int i = 0; i < 8; i++) {
        int idx = tid + i * NT;                 // 0..4095
        int r = idx >> 5, c4 = idx & 31;
        u32 xa = __float_as_uint(v[i].x);
        u32 xb = __float_as_uint(v[i].y);
        u32 xc = __float_as_uint(v[i].z);
        u32 xd = __float_as_uint(v[i].w);
        u32 h01 = prmt_hi(xa, xb);
        u32 h23 = prmt_hi(xc, xd);
        float l0 = v[i].x - __uint_as_float(xa & 0xFFFF0000u);
        float l1 = v[i].y - __uint_as_float(xb & 0xFFFF0000u);
        float l2 = v[i].z - __uint_as_float(xc & 0xFFFF0000u);
        float l3 = v[i].w - __uint_as_float(xd & 0xFFFF0000u);
        u32 L01 = pack_bf16_rn(l0, l1);
        u32 L23 = pack_bf16_rn(l2, l3);
        int off = r * (SA * 2) + 8 * c4;        // byte offset, 8B aligned
        *(ull*)(smem + OFF_AH + off) = (ull)h01 | ((ull)h23 << 32);
        *(ull*)(smem + OFF_AL + off) = (ull)L01 | ((ull)L23 << 32);
    }
}

// ---------------------------------------------------------------------------
// HMMA core: one 128-k chunk. Warp tile 32m x 32n; fragments via ldmatrix.x4.
// ---------------------------------------------------------------------------
__device__ __forceinline__ void gemm_chunk(float C[2][4][4],
                                           const u32 aah[2], const u32 aal[2],
                                           const u32 bbh[2], const u32 bbl[2],
                                           int kbase) {
#pragma unroll
    for (int s = 0; s < 8; s++) {
        int koffA = s * 32;                    // 16 elems * 2B
        int koffB = (kbase + s * 16) * 2;
        u32 ah0[4], ah1[4], al0[4], al1[4];
        u32 bh0[4], bh1[4], bl0[4], bl1[4];
        LDM4(ah0, aah[0] + koffA);
        LDM4(ah1, aah[1] + koffA);
        LDM4(al0, aal[0] + koffA);
        LDM4(al1, aal[1] + koffA);
        LDM4(bh0, bbh[0] + koffB);
        LDM4(bh1, bbh[1] + koffB);
        LDM4(bl0, bbl[0] + koffB);
        LDM4(bl1, bbl[1] + koffB);
        mma16816(C[0][0], ah0, bh0[0], bh0[2]);
        mma16816(C[0][1], ah0, bh0[1], bh0[3]);
        mma16816(C[0][2], ah0, bh1[0], bh1[2]);
        mma16816(C[0][3], ah0, bh1[1], bh1[3]);
        mma16816(C[1][0], ah1, bh0[0], bh0[2]);
        mma16816(C[1][1], ah1, bh0[1], bh0[3]);
        mma16816(C[1][2], ah1, bh1[0], bh1[2]);
        mma16816(C[1][3], ah1, bh1[1], bh1[3]);

        mma16816(C[0][0], ah0, bl0[0], bl0[2]);
        mma16816(C[0][1], ah0, bl0[1], bl0[3]);
        mma16816(C[0][2], ah0, bl1[0], bl1[2]);
        mma16816(C[0][3], ah0, bl1[1], bl1[3]);
        mma16816(C[1][0], ah1, bl0[0], bl0[2]);
        mma16816(C[1][1], ah1, bl0[1], bl0[3]);
        mma16816(C[1][2], ah1, bl1[0], bl1[2]);
        mma16816(C[1][3], ah1, bl1[1], bl1[3]);

        mma16816(C[0][0], al0, bh0[0], bh0[2]);
        mma16816(C[0][1], al0, bh0[1], bh0[3]);
        mma16816(C[0][2], al0, bh1[0], bh1[2]);
        mma16816(C[0][3], al0, bh1[1], bh1[3]);
        mma16816(C[1][0], al1, bh0[0], bh0[2]);
        mma16816(C[1][1], al1, bh0[1], bh0[3]);
        mma16816(C[1][2], al1, bh1[0], bh1[2]);
        mma16816(C[1][3], al1, bh1[1], bh1[3]);
    }
}

__device__ __forceinline__ void frag_bases(u32 sb, int wm, int wn, int lane,
                                           u32 aah[2], u32 aal[2],
                                           u32 bbh[2], u32 bbl[2]) {
    int ar = lane & 15;
    int ak = (lane >> 4) * 16;                 // byte offset for k+8 half
#pragma unroll
    for (int mt = 0; mt < 2; mt++) {
        aah[mt] = sb + OFF_AH + (u32)((wm * 32 + mt * 16 + ar) * (SA * 2)) + ak;
        aal[mt] = aah[mt] + (OFF_AL - OFF_AH);
    }
#pragma unroll
    for (int g = 0; g < 2; g++) {
        bbh[g] = sb + OFF_BH + (u32)((wn * 32 + g * 16 + ar) * (SB * 2)) + ak;
        bbl[g] = bbh[g] + (OFF_BL - OFF_BH);
    }
}

// ---------------------------------------------------------------------------
// k_scores_mma: D = X_tile @ W1 (HMMA), epilogue tanh(D+b1).W2 + b2.
// ---------------------------------------------------------------------------
__global__ __launch_bounds__(NT, 1)
void k_scores_mma(const float* __restrict__ X,
                  const float* __restrict__ W1,
                  const float* __restrict__ b1,
                  const float* __restrict__ W2,
                  const float* __restrict__ b2,
                  int n_agents) {
    extern __shared__ char smem[];
    float* b1s = (float*)(smem + OFF_VEC0);
    float* w2s = (float*)(smem + OFF_VEC1);
    float* ps  = (float*)(smem + OFF_PS);

    const int tid  = threadIdx.x;
    const int wid  = tid >> 5;
    const int lane = tid & 31;
    const int wm   = wid & 3;
    const int wn   = wid >> 2;
    const int qr   = lane >> 2;
    const int qc   = lane & 3;
    const u32 sb   = smem_u32(smem);

    u32 aah[2], aal[2], bbh[2], bbl[2];
    frag_bases(sb, wm, wn, lane, aah, aal, bbh, bbl);

    for (int i = tid; i < H2; i += NT) { b1s[i] = b1[i]; w2s[i] = W2[i]; }
    stage_B(smem, W1, H2, 0, tid);
    const float b2s = __ldg(b2);

    const int ntiles = (n_agents + 127) >> 7;
    for (int tile = blockIdx.x; tile < ntiles; tile += gridDim.x) {
        int base = tile << 7;
        float C[2][4][4];
#pragma unroll
        for (int mt = 0; mt < 2; mt++)
#pragma unroll
            for (int nt = 0; nt < 4; nt++)
#pragma unroll
                for (int j = 0; j < 4; j++) C[mt][nt][j] = 0.f;

#pragma unroll
        for (int chunk = 0; chunk < 2; chunk++) {
            float4 v[8];
            prefetch_A(v, X, base, n_agents, chunk, tid);  // overlap w/ prev MMA
            __syncthreads();           // prior readers of A / ps done
            store_A(smem, v, tid);
            __syncthreads();
            gemm_chunk(C, aah, aal, bbh, bbl, chunk * 128);
        }

        // epilogue: per-row partial of tanh(c+b1)*w2 over this warp's 32 cols
        float acc[2][2];
        acc[0][0] = acc[0][1] = acc[1][0] = acc[1][1] = 0.f;
#pragma unroll
        for (int nt = 0; nt < 4; nt++) {
            int c0 = wn * 32 + nt * 8 + 2 * qc;
            float bw0 = b1s[c0], bw1 = b1s[c0 + 1];
            float w0 = w2s[c0], w1 = w2s[c0 + 1];
#pragma unroll
            for (int mt = 0; mt < 2; mt++) {
                acc[mt][0] += tanhf(C[mt][nt][0] + bw0) * w0
                            + tanhf(C[mt][nt][1] + bw1) * w1;
                acc[mt][1] += tanhf(C[mt][nt][2] + bw0) * w0
                            + tanhf(C[mt][nt][3] + bw1) * w1;
            }
        }
#pragma unroll
        for (int mt = 0; mt < 2; mt++)
#pragma unroll
            for (int h = 0; h < 2; h++) {
                float v2 = acc[mt][h];
                v2 += __shfl_xor_sync(0xFFFFFFFFu, v2, 1);
                v2 += __shfl_xor_sync(0xFFFFFFFFu, v2, 2);
                acc[mt][h] = v2;
            }
        if (qc == 0) {
#pragma unroll
            for (int mt = 0; mt < 2; mt++) {
                int rl = wm * 32 + mt * 16 + qr;
                ps[wn * 128 + rl]     = acc[mt][0];
                ps[wn * 128 + rl + 8] = acc[mt][1];
            }
        }
        __syncthreads();
        if (tid < 128) {
            int row = base + tid;
            if (row < n_agents)
                g_scores[row] = ps[tid] + ps[128 + tid] + ps[256 + tid]
                              + ps[384 + tid] + b2s;
        }
    }
}

// ---------------------------------------------------------------------------
// k_team: one warp per team. __expf + unrolled pooling (MLP 4).
// ---------------------------------------------------------------------------
__global__ void k_team(const float* __restrict__ agent_h,
                       float* __restrict__ out_attn,
                       int n_teams) {
    int t = blockIdx.x * 8 + (threadIdx.x >> 5);
    int lane = threadIdx.x & 31;
    if (t >= n_teams) return;

    int end = g_offs[t];
    int cnt = g_counts[t];
    int start = end - cnt;

    float m = -CUDART_INF_F;
    for (int b = 0; b < cnt; b += 32) {
        int i = b + lane;
        float s = (i < cnt) ? g_scores[g_order[start + i]] : -CUDART_INF_F;
        m = fmaxf(m, s);
    }
#pragma unroll
    for (int o = 16; o > 0; o >>= 1)
        m = fmaxf(m, __shfl_xor_sync(0xFFFFFFFFu, m, o));

    float esum = 0.f;
    for (int b = 0; b < cnt; b += 32) {
        int i = b + lane;
        if (i < cnt) {
            int a = g_order[start + i];
            float e = __expf(g_scores[a] - m);
            g_scores[a] = e;
            esum += e;
        }
    }
#pragma unroll
    for (int o = 16; o > 0; o >>= 1)
        esum += __shfl_xor_sync(0xFFFFFFFFu, esum, o);
    __syncwarp();

    float inv = (cnt > 0) ? (1.f / esum) : 0.f;

    float4 acc0 = make_float4(0.f, 0.f, 0.f, 0.f);
    float4 acc1 = make_float4(0.f, 0.f, 0.f, 0.f);
    int mI = 0;
    for (; mI + 2 <= cnt; mI += 2) {
        int a0 = g_order[start + mI];
        int a1 = g_order[start + mI + 1];
        float w0 = g_scores[a0] * inv;
        float w1 = g_scores[a1] * inv;
        if (lane == 0) { out_attn[a0] = w0; out_attn[a1] = w1; }
        const float4* r0 = (const float4*)(agent_h + (size_t)a0 * HIDDEN);
        const float4* r1 = (const float4*)(agent_h + (size_t)a1 * HIDDEN);
        float4 x00 = r0[lane], x01 = r0[32 + lane];
        float4 x10 = r1[lane], x11 = r1[32 + lane];
        acc0.x += w0 * x00.x + w1 * x10.x;
        acc0.y += w0 * x00.y + w1 * x10.y;
        acc0.z += w0 * x00.z + w1 * x10.z;
        acc0.w += w0 * x00.w + w1 * x10.w;
        acc1.x += w0 * x01.x + w1 * x11.x;
        acc1.y += w0 * x01.y + w1 * x11.y;
        acc1.z += w0 * x01.z + w1 * x11.z;
        acc1.w += w0 * x01.w + w1 * x11.w;
    }
    if (mI < cnt) {
        int a = g_order[start + mI];
        float wgt = g_scores[a] * inv;
        if (lane == 0) out_attn[a] = wgt;
        const float4* row = (const float4*)(agent_h + (size_t)a * HIDDEN);
        float4 x0 = row[lane];
        float4 x1 = row[32 + lane];
        acc0.x += wgt * x0.x; acc0.y += wgt * x0.y;
        acc0.z += wgt * x0.z; acc0.w += wgt * x0.w;
        acc1.x += wgt * x1.x; acc1.y += wgt * x1.y;
        acc1.z += wgt * x1.z; acc1.w += wgt * x1.w;
    }
    float4* dst = (float4*)(g_team_pre + (size_t)t * HIDDEN);
    dst[lane]      = acc0;
    dst[32 + lane] = acc1;
}

// ---------------------------------------------------------------------------
// k_out_mma: out[:, H*128:+128] = relu(team_pre @ Wo_half + bo_half)
// ---------------------------------------------------------------------------
__global__ __launch_bounds__(NT, 1)
void k_out_mma(const float* __restrict__ Wo,
               const float* __restrict__ bo,
               float* __restrict__ out_team,
               int n_teams) {
    extern __shared__ char smem[];
    float* bos = (float*)(smem + OFF_VEC0);

    const int tid  = threadIdx.x;
    const int wid  = tid >> 5;
    const int lane = tid & 31;
    const int wm   = wid & 3;
    const int wn   = wid >> 2;
    const int qr   = lane >> 2;
    const int qc   = lane & 3;
    const int H    = blockIdx.y;
    const u32 sb   = smem_u32(smem);

    u32 aah[2], aal[2], bbh[2], bbl[2];
    frag_bases(sb, wm, wn, lane, aah, aal, bbh, bbl);

    for (int i = tid; i < H2; i += NT) bos[i] = bo[H * H2 + i];
    stage_B(smem, Wo, HIDDEN, H * H2, tid);

    const int ntiles = (n_teams + 127) >> 7;
    for (int tile = blockIdx.x; tile < ntiles; tile += gridDim.x) {
        int base = tile << 7;
        float C[2][4][4];
#pragma unroll
        for (int mt = 0; mt < 2; mt++)
#pragma unroll
            for (int nt = 0; nt < 4; nt++)
#pragma unroll
                for (int j = 0; j < 4; j++) C[mt][nt][j] = 0.f;

#pragma unroll
        for (int chunk = 0; chunk < 2; chunk++) {
            float4 v[8];
            prefetch_A(v, g_team_pre, base, n_teams, chunk, tid);
            __syncthreads();
            store_A(smem, v, tid);
            __syncthreads();
            gemm_chunk(C, aah, aal, bbh, bbl, chunk * 128);
        }

        // epilogue: relu(c + bo) -> out
#pragma unroll
        for (int mt = 0; mt < 2; mt++) {
            int r0 = base + wm * 32 + mt * 16 + qr;
#pragma unroll
            for (int nt = 0; nt < 4; nt++) {
                int cl = wn * 32 + nt * 8 + 2 * qc;
                int cg = H * H2 + cl;
                float b0 = bos[cl], b1v = bos[cl + 1];
                if (r0 < n_teams) {
                    float2 o;
                    o.x = fmaxf(C[mt][nt][0] + b0, 0.f);
                    o.y = fmaxf(C[mt][nt][1] + b1v, 0.f);
                    *(float2*)(out_team + (size_t)r0 * HIDDEN + cg) = o;
                }
                if (r0 + 8 < n_teams) {
                    float2 o;
                    o.x = fmaxf(C[mt][nt][2] + b0, 0.f);
                    o.y = fmaxf(C[mt][nt][3] + b1v, 0.f);
                    *(float2*)(out_team + (size_t)(r0 + 8) * HIDDEN + cg) = o;
                }
            }
        }
    }
}

// ---------------------------------------------------------------------------
extern "C" void kernel_launch(void* const* d_in, const int* in_sizes, int n_in,
                              void* d_out, int out_size) {
    const float* agent_h  = (const float*)d_in[0];
    const void*  team_idx = d_in[1];
    const float* W1 = (const float*)d_in[3];
    const float* b1 = (const float*)d_in[4];
    const float* W2 = (const float*)d_in[5];
    const float* b2 = (const float*)d_in[6];
    const float* Wo = (const float*)d_in[7];
    const float* bo = (const float*)d_in[8];

    const int n_agents = in_sizes[0] / HIDDEN;
    const int n_teams  = (out_size - n_agents) / HIDDEN;

    float* out_team = (float*)d_out;
    float* out_attn = out_team + (size_t)n_teams * HIDDEN;

    // one-time side stream + events (no device memory involved)
    static cudaStream_t s2 = nullptr;
    static cudaEvent_t evFork = nullptr, evJoin = nullptr;
    static bool attr_done = false;
    if (!s2) {
        cudaStreamCreateWithFlags(&s2, cudaStreamNonBlocking);
        cudaEventCreateWithFlags(&evFork, cudaEventDisableTiming);
        cudaEventCreateWithFlags(&evJoin, cudaEventDisableTiming);
    }
    if (!attr_done) {
        cudaFuncSetAttribute(k_scores_mma,
                             cudaFuncAttributeMaxDynamicSharedMemorySize, SMEM_MMA);
        cudaFuncSetAttribute(k_out_mma,
                             cudaFuncAttributeMaxDynamicSharedMemorySize, SMEM_MMA);
        attr_done = true;
    }

    const int nscan = (n_teams + 1023) / 1024;

    // fork: CSR build on s2, scores GEMM on main stream
    cudaEventRecord(evFork, 0);
    cudaStreamWaitEvent(s2, evFork, 0);

    k_detect<<<1, 256, 0, s2>>>(team_idx, n_agents, n_teams);
    k_zero_counts<<<(n_teams + 255) / 256, 256, 0, s2>>>(n_teams);
    k_count<<<(n_agents + 255) / 256, 256, 0, s2>>>(team_idx, n_agents, n_teams);
    k_scan1<<<nscan, 1024, 0, s2>>>(n_teams);
    k_scan2<<<1, 128, 0, s2>>>(nscan);
    k_scan3<<<nscan, 1024, 0, s2>>>(n_teams);
    k_fill<<<(n_agents + 255) / 256, 256, 0, s2>>>(team_idx, n_agents, n_teams);
    cudaEventRecord(evJoin, s2);

    // per-agent scores (HMMA GEMM + fused tanh/dot epilogue), main stream
    k_scores_mma<<<148, NT, SMEM_MMA>>>(agent_h, W1, b1, W2, b2, n_agents);

    // join: k_team needs both CSR and scores
    cudaStreamWaitEvent(0, evJoin, 0);
    k_team<<<(n_teams + 7) / 8, 256>>>(agent_h, out_attn, n_teams);

    // output projection + relu (HMMA GEMM), two column halves
    dim3 og(148, 2, 1);
    k_out_mma<<<og, NT, SMEM_MMA>>>(Wo, bo, out_team, n_teams);
}